// round 2
// baseline (speedup 1.0000x reference)
#include <cuda_runtime.h>
#include <cstdint>
#include <cstddef>

// ---------------- problem constants ----------------
#define S_LEN  2048
#define HID    2048
#define NHEAD  16
#define NKVH   4
#define HDIM   128
#define BATCH  2
#define ROWS   (BATCH * S_LEN)      // 4096
#define SCALE  0.08838834764831845f // 1/sqrt(128)

// ---------------- scratch (static device memory; no allocations) ----------------
__device__ float g_q[(size_t)ROWS * NHEAD * HDIM];   // 33.5 MB
__device__ float g_k[(size_t)ROWS * NKVH  * HDIM];   //  8.4 MB
__device__ float g_v[(size_t)ROWS * NKVH  * HDIM];   //  8.4 MB
__device__ float g_o[(size_t)ROWS * NHEAD * HDIM];   // 33.5 MB

// ---------------- SGEMM: C[M,N] = A[M,K] @ B[K,N], 128x128x8 tiles, 8x8 micro ----------------
__global__ void __launch_bounds__(256, 2)
sgemm128(const float* __restrict__ A, const float* __restrict__ B,
         float* __restrict__ C, int M, int N, int K)
{
    __shared__ float As[8][128];   // transposed: As[k][m]
    __shared__ float Bs[8][128];   // Bs[k][n]

    const int tid = threadIdx.x;
    const int tx  = tid & 15;      // 0..15 -> 8 cols each
    const int ty  = tid >> 4;      // 0..15 -> 8 rows each
    const int row0 = blockIdx.y * 128;
    const int col0 = blockIdx.x * 128;

    const int ar = tid >> 1;            // 0..127 (A row within tile)
    const int ac = (tid & 1) * 4;       // 0 or 4 (A col seg)
    const int bk = tid >> 5;            // 0..7   (B row within tile)
    const int bn = (tid & 31) * 4;      // 0..124 (B col seg)

    const float* Aptr = A + (size_t)(row0 + ar) * K + ac;
    const float* Bptr = B + (size_t)bk * N + col0 + bn;

    float acc[8][8];
    #pragma unroll
    for (int i = 0; i < 8; i++)
        #pragma unroll
        for (int j = 0; j < 8; j++) acc[i][j] = 0.0f;

    for (int k0 = 0; k0 < K; k0 += 8) {
        float4 a = *(const float4*)(Aptr + k0);
        float4 b = *(const float4*)(Bptr + (size_t)k0 * N);
        __syncthreads();
        As[ac + 0][ar] = a.x;
        As[ac + 1][ar] = a.y;
        As[ac + 2][ar] = a.z;
        As[ac + 3][ar] = a.w;
        *(float4*)&Bs[bk][bn] = b;
        __syncthreads();

        #pragma unroll
        for (int k = 0; k < 8; k++) {
            float ra[8], rb[8];
            *(float4*)&ra[0] = *(const float4*)&As[k][ty * 8];
            *(float4*)&ra[4] = *(const float4*)&As[k][ty * 8 + 4];
            *(float4*)&rb[0] = *(const float4*)&Bs[k][tx * 8];
            *(float4*)&rb[4] = *(const float4*)&Bs[k][tx * 8 + 4];
            #pragma unroll
            for (int i = 0; i < 8; i++)
                #pragma unroll
                for (int j = 0; j < 8; j++)
                    acc[i][j] += ra[i] * rb[j];
        }
    }

    #pragma unroll
    for (int i = 0; i < 8; i++) {
        float* Crow = C + (size_t)(row0 + ty * 8 + i) * N + col0 + tx * 8;
        *(float4*)(Crow)     = make_float4(acc[i][0], acc[i][1], acc[i][2], acc[i][3]);
        *(float4*)(Crow + 4) = make_float4(acc[i][4], acc[i][5], acc[i][6], acc[i][7]);
    }
}

// ---------------- RoPE (in place), double-precision trig for safety ----------------
// t: [rows, nheads*128]; element pair (d, d+64) per head; pos = row % S_LEN
__global__ void rope_kernel(float* __restrict__ t, int total, int nheads)
{
    int idx = blockIdx.x * blockDim.x + threadIdx.x;
    if (idx >= total) return;
    int d   = idx & 63;
    int tmp = idx >> 6;
    int h   = tmp % nheads;
    int row = tmp / nheads;
    int pos = row & (S_LEN - 1);

    double inv = pow(10000.0, -((double)(2 * d)) / 128.0);
    double ang = (double)pos * inv;
    double cd, sd;
    sincos(ang, &sd, &cd);
    float c = (float)cd;
    float s = (float)sd;

    float* base = t + ((size_t)row * nheads + h) * HDIM;
    float x1 = base[d];
    float x2 = base[d + 64];
    base[d]      = x1 * c - x2 * s;
    base[d + 64] = x2 * c + x1 * s;
}

// ---------------- attention (causal, GQA), fp32, warp-per-4-rows ----------------
// grid: (S/32, NH, B); block 256 = 8 warps; warp w owns block-local rows w*4..w*4+3.
// lane = key column within the 32-wide K tile -> all softmax reductions are
// full-warp (32 lanes, one row), no half-warp subtleties. P stays in registers.
// smem: sQ[32][132] + sK[32][132] + sV[32][132] = 50688 B
#define PITCH 132
__global__ void __launch_bounds__(256)
attn_simple(const float* __restrict__ Q, const float* __restrict__ K,
            const float* __restrict__ V, float* __restrict__ O)
{
    const int qt = blockIdx.x;     // 0..63 (32 q-rows per block)
    const int h  = blockIdx.y;     // 0..15
    const int b  = blockIdx.z;     // 0..1
    const int g  = h >> 2;         // kv group (N_REP = 4)

    extern __shared__ float sm[];
    float* sQ = sm;                    // [32][PITCH]
    float* sK = sm + 32 * PITCH;
    float* sV = sm + 2 * 32 * PITCH;

    const int tid  = threadIdx.x;
    const int wid  = tid >> 5;     // 0..7
    const int lane = tid & 31;
    const int r0   = wid * 4;      // this warp's first block-local row

    // ---- load Q tile: 32 rows x 128 dims ----
    const float* Qb = Q + ((size_t)(b * S_LEN + qt * 32)) * (NHEAD * HDIM) + h * HDIM;
    #pragma unroll
    for (int it = 0; it < 4; it++) {
        int idx = tid + it * 256;          // 0..1023
        int r   = idx >> 5;                // 0..31
        int seg = (idx & 31) * 4;          // 0..124
        float4 q4 = *(const float4*)(Qb + (size_t)r * (NHEAD * HDIM) + seg);
        *(float4*)&sQ[r * PITCH + seg] = q4;
    }

    float m[4], l[4], acc[4][4], p[4];
    #pragma unroll
    for (int i = 0; i < 4; i++) {
        m[i] = -1e30f; l[i] = 0.0f;
        acc[i][0] = acc[i][1] = acc[i][2] = acc[i][3] = 0.0f;
    }

    const int nkt = qt + 1;   // causal: K tiles 0..qt
    for (int kt = 0; kt < nkt; kt++) {
        __syncthreads();      // prev PV reads of sV done before overwrite
        const float* Kb = K + ((size_t)(b * S_LEN + kt * 32)) * (NKVH * HDIM) + g * HDIM;
        const float* Vb = V + ((size_t)(b * S_LEN + kt * 32)) * (NKVH * HDIM) + g * HDIM;
        #pragma unroll
        for (int it = 0; it < 8; it++) {
            int idx = tid + it * 256;      // 0..2047; <1024 -> K, else V
            int r   = (idx >> 5) & 31;
            int seg = (idx & 31) * 4;
            if (idx < 1024) {
                *(float4*)&sK[r * PITCH + seg] =
                    *(const float4*)(Kb + (size_t)r * (NKVH * HDIM) + seg);
            } else {
                *(float4*)&sV[r * PITCH + seg] =
                    *(const float4*)(Vb + (size_t)r * (NKVH * HDIM) + seg);
            }
        }
        __syncthreads();

        // ---- scores: s4[i] = dot(Q[r0+i], K[lane]) over 128 dims ----
        float s4[4] = {0.0f, 0.0f, 0.0f, 0.0f};
        #pragma unroll 8
        for (int d4 = 0; d4 < 32; d4++) {
            float4 kv = *(const float4*)&sK[lane * PITCH + d4 * 4];
            #pragma unroll
            for (int i = 0; i < 4; i++) {
                float4 qv = *(const float4*)&sQ[(r0 + i) * PITCH + d4 * 4];
                s4[i] += qv.x * kv.x + qv.y * kv.y + qv.z * kv.z + qv.w * kv.w;
            }
        }

        // ---- online softmax per row (full-warp reductions) ----
        const int gcol = kt * 32 + lane;
        #pragma unroll
        for (int i = 0; i < 4; i++) {
            const int grow = qt * 32 + r0 + i;
            float sv = s4[i] * SCALE;
            if (gcol > grow) sv = -1e9f;   // causal mask
            float mx = sv;
            #pragma unroll
            for (int o = 16; o > 0; o >>= 1)
                mx = fmaxf(mx, __shfl_xor_sync(0xffffffffu, mx, o));
            float mnew = fmaxf(m[i], mx);
            float corr = __expf(m[i] - mnew);
            float pv   = __expf(sv - mnew);
            float ls = pv;
            #pragma unroll
            for (int o = 16; o > 0; o >>= 1)
                ls += __shfl_xor_sync(0xffffffffu, ls, o);
            l[i] = l[i] * corr + ls;
            m[i] = mnew;
            p[i] = pv;
            acc[i][0] *= corr; acc[i][1] *= corr;
            acc[i][2] *= corr; acc[i][3] *= corr;
        }

        // ---- PV: acc[i][dd] += P[i][c] * V[c][lane*4+dd] ----
        #pragma unroll 8
        for (int c = 0; c < 32; c++) {
            float4 v4 = *(const float4*)&sV[c * PITCH + lane * 4];
            #pragma unroll
            for (int i = 0; i < 4; i++) {
                float pc = __shfl_sync(0xffffffffu, p[i], c);
                acc[i][0] += pc * v4.x;
                acc[i][1] += pc * v4.y;
                acc[i][2] += pc * v4.z;
                acc[i][3] += pc * v4.w;
            }
        }
    }

    // ---- epilogue: normalize and store (lane owns dims lane*4..lane*4+3) ----
    float* Ob = O + ((size_t)(b * S_LEN + qt * 32)) * (NHEAD * HDIM) + h * HDIM;
    #pragma unroll
    for (int i = 0; i < 4; i++) {
        float inv_l = 1.0f / l[i];
        *(float4*)(Ob + (size_t)(r0 + i) * (NHEAD * HDIM) + lane * 4) =
            make_float4(acc[i][0] * inv_l, acc[i][1] * inv_l,
                        acc[i][2] * inv_l, acc[i][3] * inv_l);
    }
}

// ---------------- launch ----------------
extern "C" void kernel_launch(void* const* d_in, const int* in_sizes, int n_in,
                              void* d_out, int out_size)
{
    const float* x  = (const float*)d_in[0];
    const float* wq = (const float*)d_in[1];
    const float* wk = (const float*)d_in[2];
    const float* wv = (const float*)d_in[3];
    const float* wo = (const float*)d_in[4];
    float* out = (float*)d_out;

    float *q_ptr, *k_ptr, *v_ptr, *o_ptr;
    cudaGetSymbolAddress((void**)&q_ptr, g_q);
    cudaGetSymbolAddress((void**)&k_ptr, g_k);
    cudaGetSymbolAddress((void**)&v_ptr, g_v);
    cudaGetSymbolAddress((void**)&o_ptr, g_o);

    // 1. QKV projections
    sgemm128<<<dim3(HID / 128, ROWS / 128), 256>>>(x, wq, q_ptr, ROWS, NHEAD * HDIM, HID);
    sgemm128<<<dim3((NKVH * HDIM) / 128, ROWS / 128), 256>>>(x, wk, k_ptr, ROWS, NKVH * HDIM, HID);
    sgemm128<<<dim3((NKVH * HDIM) / 128, ROWS / 128), 256>>>(x, wv, v_ptr, ROWS, NKVH * HDIM, HID);

    // 2. RoPE on q and k
    {
        int total_q = ROWS * NHEAD * 64;
        rope_kernel<<<(total_q + 255) / 256, 256>>>(q_ptr, total_q, NHEAD);
        int total_k = ROWS * NKVH * 64;
        rope_kernel<<<(total_k + 255) / 256, 256>>>(k_ptr, total_k, NKVH);
    }

    // 3. attention
    {
        int smem = 3 * 32 * PITCH * (int)sizeof(float); // 50688 B
        cudaFuncSetAttribute(attn_simple, cudaFuncAttributeMaxDynamicSharedMemorySize, smem);
        attn_simple<<<dim3(S_LEN / 32, NHEAD, BATCH), 256, smem>>>(q_ptr, k_ptr, v_ptr, o_ptr);
    }

    // 4. output projection
    sgemm128<<<dim3(HID / 128, ROWS / 128), 256>>>(o_ptr, wo, out, ROWS, HID, HID);
}

// round 3
// speedup vs baseline: 1.3804x; 1.3804x over previous
#include <cuda_runtime.h>
#include <cstdint>
#include <cstddef>

// ---------------- problem constants ----------------
#define S_LEN  2048
#define HID    2048
#define NHEAD  16
#define NKVH   4
#define HDIM   128
#define BATCH  2
#define ROWS   (BATCH * S_LEN)      // 4096
#define SCALE  0.08838834764831845f // 1/sqrt(128)

// ---------------- scratch (static device memory; no allocations) ----------------
__device__ float g_q[(size_t)ROWS * NHEAD * HDIM];   // 33.5 MB
__device__ float g_k[(size_t)ROWS * NKVH  * HDIM];   //  8.4 MB
__device__ float g_v[(size_t)ROWS * NKVH  * HDIM];   //  8.4 MB
__device__ float g_o[(size_t)ROWS * NHEAD * HDIM];   // 33.5 MB
__device__ float2 g_rope_tab[(size_t)S_LEN * 64];    // cos/sin per (pos, d)

// ---------------- rope table fill (double precision, 131K threads, cheap) ----------------
__global__ void fill_rope_table()
{
    int idx = blockIdx.x * blockDim.x + threadIdx.x;
    if (idx >= S_LEN * 64) return;
    int d   = idx & 63;
    int pos = idx >> 6;
    double inv = pow(10000.0, -((double)(2 * d)) / 128.0);
    double ang = (double)pos * inv;
    double cd, sd;
    sincos(ang, &sd, &cd);
    g_rope_tab[idx] = make_float2((float)cd, (float)sd);
}

// ---------------- RoPE apply (in place, table lookup, bandwidth-bound) ----------------
// t: [rows, nheads*128]; element pair (d, d+64) per head; pos = row % S_LEN
__global__ void rope_apply(float* __restrict__ t, int total, int nheads)
{
    int idx = blockIdx.x * blockDim.x + threadIdx.x;
    if (idx >= total) return;
    int d   = idx & 63;
    int tmp = idx >> 6;
    int h   = tmp % nheads;
    int row = tmp / nheads;
    int pos = row & (S_LEN - 1);

    float2 cs = g_rope_tab[pos * 64 + d];

    float* base = t + ((size_t)row * nheads + h) * HDIM;
    float x1 = base[d];
    float x2 = base[d + 64];
    base[d]      = x1 * cs.x - x2 * cs.y;
    base[d + 64] = x2 * cs.x + x1 * cs.y;
}

// ---------------- double-buffered SGEMM body: C[*,N] tile at (row0,col0), K-dim K ----------------
// block = 256 threads, tile 128x128, K-step 8, 8x8 micro-tile per thread.
__device__ __forceinline__ void gemm_body(
    const float* __restrict__ A, const float* __restrict__ B, float* __restrict__ C,
    int N, int K, int row0, int col0,
    float As[2][8][128], float Bs[2][8][128])
{
    const int tid = threadIdx.x;
    const int tx  = tid & 15;
    const int ty  = tid >> 4;

    const int ar = tid >> 1;            // 0..127 (A row within tile)
    const int ac = (tid & 1) * 4;       // 0 or 4 (A col seg)
    const int bk = tid >> 5;            // 0..7   (B row within tile)
    const int bn = (tid & 31) * 4;      // 0..124 (B col seg)

    const float* Aptr = A + (size_t)(row0 + ar) * K + ac;
    const float* Bptr = B + (size_t)bk * N + col0 + bn;

    float acc[8][8];
    #pragma unroll
    for (int i = 0; i < 8; i++)
        #pragma unroll
        for (int j = 0; j < 8; j++) acc[i][j] = 0.0f;

    // preload k0 = 0 into buffer 0
    {
        float4 a = *(const float4*)(Aptr);
        float4 b = *(const float4*)(Bptr);
        As[0][ac + 0][ar] = a.x;
        As[0][ac + 1][ar] = a.y;
        As[0][ac + 2][ar] = a.z;
        As[0][ac + 3][ar] = a.w;
        *(float4*)&Bs[0][bk][bn] = b;
    }
    __syncthreads();

    int cur = 0;
    for (int k0 = 0; k0 < K; k0 += 8) {
        const bool has_next = (k0 + 8) < K;
        float4 an, bn4;
        if (has_next) {
            an  = *(const float4*)(Aptr + k0 + 8);
            bn4 = *(const float4*)(Bptr + (size_t)(k0 + 8) * N);
        }

        #pragma unroll
        for (int k = 0; k < 8; k++) {
            float ra[8], rb[8];
            *(float4*)&ra[0] = *(const float4*)&As[cur][k][ty * 8];
            *(float4*)&ra[4] = *(const float4*)&As[cur][k][ty * 8 + 4];
            *(float4*)&rb[0] = *(const float4*)&Bs[cur][k][tx * 8];
            *(float4*)&rb[4] = *(const float4*)&Bs[cur][k][tx * 8 + 4];
            #pragma unroll
            for (int i = 0; i < 8; i++)
                #pragma unroll
                for (int j = 0; j < 8; j++)
                    acc[i][j] += ra[i] * rb[j];
        }

        if (has_next) {
            const int nxt = cur ^ 1;
            As[nxt][ac + 0][ar] = an.x;
            As[nxt][ac + 1][ar] = an.y;
            As[nxt][ac + 2][ar] = an.z;
            As[nxt][ac + 3][ar] = an.w;
            *(float4*)&Bs[nxt][bk][bn] = bn4;
        }
        __syncthreads();
        cur ^= 1;
    }

    #pragma unroll
    for (int i = 0; i < 8; i++) {
        float* Crow = C + (size_t)(row0 + ty * 8 + i) * N + col0 + tx * 8;
        *(float4*)(Crow)     = make_float4(acc[i][0], acc[i][1], acc[i][2], acc[i][3]);
        *(float4*)(Crow + 4) = make_float4(acc[i][4], acc[i][5], acc[i][6], acc[i][7]);
    }
}

// ---------------- fused QKV projection: one grid covers wq|wk|wv column blocks ----------------
// grid.x: 0..15 -> wq (N=2048), 16..19 -> wk (N=512), 20..23 -> wv (N=512); grid.y = row tiles
__global__ void __launch_bounds__(256, 2)
qkv_gemm(const float* __restrict__ x,
         const float* __restrict__ wq, const float* __restrict__ wk, const float* __restrict__ wv,
         float* __restrict__ q, float* __restrict__ k, float* __restrict__ v)
{
    __shared__ float As[2][8][128];
    __shared__ float Bs[2][8][128];

    const int bx = blockIdx.x;
    const float* B; float* C; int N; int col0;
    if (bx < 16)      { B = wq; C = q; N = NHEAD * HDIM; col0 = bx * 128; }
    else if (bx < 20) { B = wk; C = k; N = NKVH * HDIM;  col0 = (bx - 16) * 128; }
    else              { B = wv; C = v; N = NKVH * HDIM;  col0 = (bx - 20) * 128; }

    gemm_body(x, B, C, N, HID, blockIdx.y * 128, col0, As, Bs);
}

// ---------------- generic SGEMM (for output projection) ----------------
__global__ void __launch_bounds__(256, 2)
sgemm128(const float* __restrict__ A, const float* __restrict__ B,
         float* __restrict__ C, int M, int N, int K)
{
    __shared__ float As[2][8][128];
    __shared__ float Bs[2][8][128];
    gemm_body(A, B, C, N, K, blockIdx.y * 128, blockIdx.x * 128, As, Bs);
}

// ---------------- attention (causal, GQA), fp32, warp-per-4-rows ----------------
// grid: (S/32, NH, B); block 256 = 8 warps; warp w owns block-local rows w*4..w*4+3.
#define PITCH 132
__global__ void __launch_bounds__(256)
attn_simple(const float* __restrict__ Q, const float* __restrict__ K,
            const float* __restrict__ V, float* __restrict__ O)
{
    const int qt = blockIdx.x;     // 0..63 (32 q-rows per block)
    const int h  = blockIdx.y;     // 0..15
    const int b  = blockIdx.z;     // 0..1
    const int g  = h >> 2;         // kv group (N_REP = 4)

    extern __shared__ float sm[];
    float* sQ = sm;                    // [32][PITCH]
    float* sK = sm + 32 * PITCH;
    float* sV = sm + 2 * 32 * PITCH;

    const int tid  = threadIdx.x;
    const int wid  = tid >> 5;     // 0..7
    const int lane = tid & 31;
    const int r0   = wid * 4;      // this warp's first block-local row

    // ---- load Q tile: 32 rows x 128 dims ----
    const float* Qb = Q + ((size_t)(b * S_LEN + qt * 32)) * (NHEAD * HDIM) + h * HDIM;
    #pragma unroll
    for (int it = 0; it < 4; it++) {
        int idx = tid + it * 256;          // 0..1023
        int r   = idx >> 5;                // 0..31
        int seg = (idx & 31) * 4;          // 0..124
        float4 q4 = *(const float4*)(Qb + (size_t)r * (NHEAD * HDIM) + seg);
        *(float4*)&sQ[r * PITCH + seg] = q4;
    }

    float m[4], l[4], acc[4][4], p[4];
    #pragma unroll
    for (int i = 0; i < 4; i++) {
        m[i] = -1e30f; l[i] = 0.0f;
        acc[i][0] = acc[i][1] = acc[i][2] = acc[i][3] = 0.0f;
    }

    const int nkt = qt + 1;   // causal: K tiles 0..qt
    for (int kt = 0; kt < nkt; kt++) {
        __syncthreads();      // prev PV reads of sV done before overwrite
        const float* Kb = K + ((size_t)(b * S_LEN + kt * 32)) * (NKVH * HDIM) + g * HDIM;
        const float* Vb = V + ((size_t)(b * S_LEN + kt * 32)) * (NKVH * HDIM) + g * HDIM;
        #pragma unroll
        for (int it = 0; it < 8; it++) {
            int idx = tid + it * 256;      // 0..2047; <1024 -> K, else V
            int r   = (idx >> 5) & 31;
            int seg = (idx & 31) * 4;
            if (idx < 1024) {
                *(float4*)&sK[r * PITCH + seg] =
                    *(const float4*)(Kb + (size_t)r * (NKVH * HDIM) + seg);
            } else {
                *(float4*)&sV[r * PITCH + seg] =
                    *(const float4*)(Vb + (size_t)r * (NKVH * HDIM) + seg);
            }
        }
        __syncthreads();

        // ---- scores: s4[i] = dot(Q[r0+i], K[lane]) over 128 dims ----
        float s4[4] = {0.0f, 0.0f, 0.0f, 0.0f};
        #pragma unroll 8
        for (int d4 = 0; d4 < 32; d4++) {
            float4 kv = *(const float4*)&sK[lane * PITCH + d4 * 4];
            #pragma unroll
            for (int i = 0; i < 4; i++) {
                float4 qv = *(const float4*)&sQ[(r0 + i) * PITCH + d4 * 4];
                s4[i] += qv.x * kv.x + qv.y * kv.y + qv.z * kv.z + qv.w * kv.w;
            }
        }

        // ---- online softmax per row (full-warp reductions) ----
        const int gcol = kt * 32 + lane;
        #pragma unroll
        for (int i = 0; i < 4; i++) {
            const int grow = qt * 32 + r0 + i;
            float sv = s4[i] * SCALE;
            if (gcol > grow) sv = -1e9f;   // causal mask
            float mx = sv;
            #pragma unroll
            for (int o = 16; o > 0; o >>= 1)
                mx = fmaxf(mx, __shfl_xor_sync(0xffffffffu, mx, o));
            float mnew = fmaxf(m[i], mx);
            float corr = __expf(m[i] - mnew);
            float pv   = __expf(sv - mnew);
            float ls = pv;
            #pragma unroll
            for (int o = 16; o > 0; o >>= 1)
                ls += __shfl_xor_sync(0xffffffffu, ls, o);
            l[i] = l[i] * corr + ls;
            m[i] = mnew;
            p[i] = pv;
            acc[i][0] *= corr; acc[i][1] *= corr;
            acc[i][2] *= corr; acc[i][3] *= corr;
        }

        // ---- PV: acc[i][dd] += P[i][c] * V[c][lane*4+dd] ----
        #pragma unroll 8
        for (int c = 0; c < 32; c++) {
            float4 v4 = *(const float4*)&sV[c * PITCH + lane * 4];
            #pragma unroll
            for (int i = 0; i < 4; i++) {
                float pc = __shfl_sync(0xffffffffu, p[i], c);
                acc[i][0] += pc * v4.x;
                acc[i][1] += pc * v4.y;
                acc[i][2] += pc * v4.z;
                acc[i][3] += pc * v4.w;
            }
        }
    }

    // ---- epilogue: normalize and store (lane owns dims lane*4..lane*4+3) ----
    float* Ob = O + ((size_t)(b * S_LEN + qt * 32)) * (NHEAD * HDIM) + h * HDIM;
    #pragma unroll
    for (int i = 0; i < 4; i++) {
        float inv_l = 1.0f / l[i];
        *(float4*)(Ob + (size_t)(r0 + i) * (NHEAD * HDIM) + lane * 4) =
            make_float4(acc[i][0] * inv_l, acc[i][1] * inv_l,
                        acc[i][2] * inv_l, acc[i][3] * inv_l);
    }
}

// ---------------- launch ----------------
extern "C" void kernel_launch(void* const* d_in, const int* in_sizes, int n_in,
                              void* d_out, int out_size)
{
    const float* x  = (const float*)d_in[0];
    const float* wq = (const float*)d_in[1];
    const float* wk = (const float*)d_in[2];
    const float* wv = (const float*)d_in[3];
    const float* wo = (const float*)d_in[4];
    float* out = (float*)d_out;

    float *q_ptr, *k_ptr, *v_ptr, *o_ptr;
    cudaGetSymbolAddress((void**)&q_ptr, g_q);
    cudaGetSymbolAddress((void**)&k_ptr, g_k);
    cudaGetSymbolAddress((void**)&v_ptr, g_v);
    cudaGetSymbolAddress((void**)&o_ptr, g_o);

    // 0. rope table (double-precision, tiny)
    fill_rope_table<<<(S_LEN * 64 + 255) / 256, 256>>>();

    // 1. fused QKV projections
    qkv_gemm<<<dim3(24, ROWS / 128), 256>>>(x, wq, wk, wv, q_ptr, k_ptr, v_ptr);

    // 2. RoPE on q and k (table lookup)
    {
        int total_q = ROWS * NHEAD * 64;
        rope_apply<<<(total_q + 255) / 256, 256>>>(q_ptr, total_q, NHEAD);
        int total_k = ROWS * NKVH * 64;
        rope_apply<<<(total_k + 255) / 256, 256>>>(k_ptr, total_k, NKVH);
    }

    // 3. attention
    {
        int smem = 3 * 32 * PITCH * (int)sizeof(float); // 50688 B
        cudaFuncSetAttribute(attn_simple, cudaFuncAttributeMaxDynamicSharedMemorySize, smem);
        attn_simple<<<dim3(S_LEN / 32, NHEAD, BATCH), 256, smem>>>(q_ptr, k_ptr, v_ptr, o_ptr);
    }

    // 4. output projection
    sgemm128<<<dim3(HID / 128, ROWS / 128), 256>>>(o_ptr, wo, out, ROWS, HID, HID);
}

// round 5
// speedup vs baseline: 1.8137x; 1.3138x over previous
#include <cuda_runtime.h>
#include <cuda_bf16.h>
#include <cstdint>
#include <cstddef>

// ---------------- problem constants ----------------
#define S_LEN  2048
#define HID    2048
#define NHEAD  16
#define NKVH   4
#define HDIM   128
#define BATCH  2
#define ROWS   (BATCH * S_LEN)      // 4096
#define SCALE  0.08838834764831845f // 1/sqrt(128)

// ---------------- scratch (static device memory; no allocations) ----------------
__device__ float g_q[(size_t)ROWS * NHEAD * HDIM];
__device__ float g_k[(size_t)ROWS * NKVH  * HDIM];
__device__ float g_v[(size_t)ROWS * NKVH  * HDIM];
__device__ float g_o[(size_t)ROWS * NHEAD * HDIM];
__device__ float2 g_rope_tab[(size_t)S_LEN * 64];

// split-bf16 operands (hi/lo). A-operands keep [M][K]; weights transposed to [N][K].
__device__ unsigned short g_xh[(size_t)ROWS * HID];
__device__ unsigned short g_xl[(size_t)ROWS * HID];
__device__ unsigned short g_oh[(size_t)ROWS * HID];
__device__ unsigned short g_ol[(size_t)ROWS * HID];
__device__ unsigned short g_wqh[(size_t)2048 * HID];
__device__ unsigned short g_wql[(size_t)2048 * HID];
__device__ unsigned short g_wkh[(size_t)512 * HID];
__device__ unsigned short g_wkl[(size_t)512 * HID];
__device__ unsigned short g_wvh[(size_t)512 * HID];
__device__ unsigned short g_wvl[(size_t)512 * HID];
__device__ unsigned short g_woh[(size_t)2048 * HID];
__device__ unsigned short g_wol[(size_t)2048 * HID];

// ================= mma.sync helper (sm_80+ feature, safe under compute_103) =================
__device__ __forceinline__ void mma_bf16(float* c, const uint32_t* a, const uint32_t* b)
{
    asm volatile(
        "mma.sync.aligned.m16n8k16.row.col.f32.bf16.bf16.f32 "
        "{%0,%1,%2,%3}, {%4,%5,%6,%7}, {%8,%9}, {%0,%1,%2,%3};"
        : "+f"(c[0]), "+f"(c[1]), "+f"(c[2]), "+f"(c[3])
        : "r"(a[0]), "r"(a[1]), "r"(a[2]), "r"(a[3]), "r"(b[0]), "r"(b[1]));
}

// ================= conversion kernels =================
__device__ __forceinline__ void bf16_split(float v, unsigned short& h, unsigned short& l) {
    __nv_bfloat16 hb = __float2bfloat16(v);
    __nv_bfloat16 lb = __float2bfloat16(v - __bfloat162float(hb));
    h = *(unsigned short*)&hb;
    l = *(unsigned short*)&lb;
}

__global__ void convert_split_k(const float* __restrict__ src,
                                unsigned short* __restrict__ hi,
                                unsigned short* __restrict__ lo, int total)
{
    int i = blockIdx.x * blockDim.x + threadIdx.x;
    if (i >= total) return;
    bf16_split(src[i], hi[i], lo[i]);
}

// src [K][N] fp32 -> hi/lo [N][K] bf16 (transpose + split)
__global__ void transpose_split_k(const float* __restrict__ src,
                                  unsigned short* __restrict__ hi,
                                  unsigned short* __restrict__ lo, int K, int N)
{
    __shared__ float t[32][33];
    const int n0 = blockIdx.x * 32, k0 = blockIdx.y * 32;
    const int tx = threadIdx.x, ty = threadIdx.y; // (32, 8)
    #pragma unroll
    for (int i = 0; i < 4; i++)
        t[ty + i * 8][tx] = src[(size_t)(k0 + ty + i * 8) * N + n0 + tx];
    __syncthreads();
    #pragma unroll
    for (int i = 0; i < 4; i++) {
        int n = ty + i * 8;
        float v = t[tx][n];
        unsigned short h, l;
        bf16_split(v, h, l);
        size_t o = (size_t)(n0 + n) * K + k0 + tx;
        hi[o] = h; lo[o] = l;
    }
}

// ================= split-bf16 GEMM via mma.sync =================
// C[128x128] CTA tile; C = A[M][2048] x B^T (B stored [N][K=2048]).
// 8 warps: warp tile 64x32 (wm = wid&1 row half, wn = wid>>2..).
// smem per buffer: Ah|Al|Bh|Bl, each 128 rows x 40 uint16 (pitch 80B, bank-clean).
#define KTILE    32
#define NT_STEPS (HID / KTILE)     // 64
#define APITCH   40                // uint16 per smem row
#define TILE_U16 (128 * APITCH)    // 5120 ushort per array
#define BUF_U16  (4 * TILE_U16)    // 20480 ushort per buffer
#define GEMM_SMEM (2 * BUF_U16 * 2)  // bytes = 81920

__device__ void gemm_mma_body(const unsigned short* __restrict__ Ah, const unsigned short* __restrict__ Al,
                              const unsigned short* __restrict__ Bh, const unsigned short* __restrict__ Bl,
                              float* __restrict__ C, int ldc, int row0, int col0)
{
    extern __shared__ unsigned short sm[];
    const int tid  = threadIdx.x;
    const int wid  = tid >> 5;
    const int lane = tid & 31;
    const int wm   = wid & 1;       // row half (0/1) -> 64 rows
    const int wn   = wid >> 1;      // col quarter (0..3) -> 32 cols
    const int g    = lane >> 2;     // 0..7
    const int tq   = lane & 3;      // 0..3

    // global tile loader mapping: thread covers row r, 32B segment `half`
    const int r    = tid >> 1;
    const int half = tid & 1;
    const unsigned short* pAh = Ah + (size_t)(row0 + r) * HID + half * 16;
    const unsigned short* pAl = Al + (size_t)(row0 + r) * HID + half * 16;
    const unsigned short* pBh = Bh + (size_t)(col0 + r) * HID + half * 16;
    const unsigned short* pBl = Bl + (size_t)(col0 + r) * HID + half * 16;
    const uint32_t soff = (uint32_t)(r * APITCH + half * 16);   // ushort units

    float acc[4][4][4];
    #pragma unroll
    for (int mi = 0; mi < 4; mi++)
        #pragma unroll
        for (int ni = 0; ni < 4; ni++)
            #pragma unroll
            for (int e = 0; e < 4; e++) acc[mi][ni][e] = 0.0f;

    // preload k-tile 0 into buffer 0
    {
        unsigned short* b0 = sm;
        *(uint4*)(b0 + soff)                 = *(const uint4*)(pAh);
        *(uint4*)(b0 + soff + 8)             = *(const uint4*)(pAh + 8);
        *(uint4*)(b0 + TILE_U16 + soff)      = *(const uint4*)(pAl);
        *(uint4*)(b0 + TILE_U16 + soff + 8)  = *(const uint4*)(pAl + 8);
        *(uint4*)(b0 + 2*TILE_U16 + soff)    = *(const uint4*)(pBh);
        *(uint4*)(b0 + 2*TILE_U16 + soff + 8)= *(const uint4*)(pBh + 8);
        *(uint4*)(b0 + 3*TILE_U16 + soff)    = *(const uint4*)(pBl);
        *(uint4*)(b0 + 3*TILE_U16 + soff + 8)= *(const uint4*)(pBl + 8);
    }
    __syncthreads();

    for (int t = 0; t < NT_STEPS; t++) {
        const int cur = t & 1;
        const bool has_next = (t + 1) < NT_STEPS;
        uint4 nAh0, nAh1, nAl0, nAl1, nBh0, nBh1, nBl0, nBl1;
        if (has_next) {
            const int kn = (t + 1) * KTILE;
            nAh0 = *(const uint4*)(pAh + kn); nAh1 = *(const uint4*)(pAh + kn + 8);
            nAl0 = *(const uint4*)(pAl + kn); nAl1 = *(const uint4*)(pAl + kn + 8);
            nBh0 = *(const uint4*)(pBh + kn); nBh1 = *(const uint4*)(pBh + kn + 8);
            nBl0 = *(const uint4*)(pBl + kn); nBl1 = *(const uint4*)(pBl + kn + 8);
        }

        const unsigned short* sa_h = sm + cur * BUF_U16;
        const unsigned short* sa_l = sa_h + TILE_U16;
        const unsigned short* sb_h = sa_h + 2 * TILE_U16;
        const unsigned short* sb_l = sa_h + 3 * TILE_U16;

        #pragma unroll
        for (int ks = 0; ks < KTILE; ks += 16) {
            uint32_t ah[4][4], al[4][4], bh[4][2], bl[4][2];
            #pragma unroll
            for (int mi = 0; mi < 4; mi++) {
                const int arow = (wm * 64 + mi * 16 + g) * APITCH + ks + tq * 2;
                ah[mi][0] = *(const uint32_t*)(sa_h + arow);
                ah[mi][1] = *(const uint32_t*)(sa_h + arow + 8 * APITCH);
                ah[mi][2] = *(const uint32_t*)(sa_h + arow + 8);
                ah[mi][3] = *(const uint32_t*)(sa_h + arow + 8 * APITCH + 8);
                al[mi][0] = *(const uint32_t*)(sa_l + arow);
                al[mi][1] = *(const uint32_t*)(sa_l + arow + 8 * APITCH);
                al[mi][2] = *(const uint32_t*)(sa_l + arow + 8);
                al[mi][3] = *(const uint32_t*)(sa_l + arow + 8 * APITCH + 8);
            }
            #pragma unroll
            for (int ni = 0; ni < 4; ni++) {
                const int brow = (wn * 32 + ni * 8 + g) * APITCH + ks + tq * 2;
                bh[ni][0] = *(const uint32_t*)(sb_h + brow);
                bh[ni][1] = *(const uint32_t*)(sb_h + brow + 8);
                bl[ni][0] = *(const uint32_t*)(sb_l + brow);
                bl[ni][1] = *(const uint32_t*)(sb_l + brow + 8);
            }
            #pragma unroll
            for (int mi = 0; mi < 4; mi++)
                #pragma unroll
                for (int ni = 0; ni < 4; ni++) {
                    mma_bf16(acc[mi][ni], ah[mi], bh[ni]);
                    mma_bf16(acc[mi][ni], ah[mi], bl[ni]);
                    mma_bf16(acc[mi][ni], al[mi], bh[ni]);
                }
        }

        if (has_next) {
            unsigned short* bn = sm + (cur ^ 1) * BUF_U16;
            *(uint4*)(bn + soff)                  = nAh0;
            *(uint4*)(bn + soff + 8)              = nAh1;
            *(uint4*)(bn + TILE_U16 + soff)       = nAl0;
            *(uint4*)(bn + TILE_U16 + soff + 8)   = nAl1;
            *(uint4*)(bn + 2*TILE_U16 + soff)     = nBh0;
            *(uint4*)(bn + 2*TILE_U16 + soff + 8) = nBh1;
            *(uint4*)(bn + 3*TILE_U16 + soff)     = nBl0;
            *(uint4*)(bn + 3*TILE_U16 + soff + 8) = nBl1;
        }
        __syncthreads();
    }

    // epilogue
    #pragma unroll
    for (int mi = 0; mi < 4; mi++) {
        const int mrow = row0 + wm * 64 + mi * 16 + g;
        #pragma unroll
        for (int ni = 0; ni < 4; ni++) {
            const int ncol = col0 + wn * 32 + ni * 8 + tq * 2;
            *(float2*)(C + (size_t)mrow * ldc + ncol)       = make_float2(acc[mi][ni][0], acc[mi][ni][1]);
            *(float2*)(C + (size_t)(mrow + 8) * ldc + ncol) = make_float2(acc[mi][ni][2], acc[mi][ni][3]);
        }
    }
}

// fused QKV: grid.x 0..15 -> q cols, 16..19 -> k cols, 20..23 -> v cols
__global__ void __launch_bounds__(256, 1)
qkv_tc(const unsigned short* xh, const unsigned short* xl,
       const unsigned short* wqh, const unsigned short* wql,
       const unsigned short* wkh, const unsigned short* wkl,
       const unsigned short* wvh, const unsigned short* wvl,
       float* q, float* k, float* v)
{
    const int bx = blockIdx.x;
    const unsigned short *Bh, *Bl; float* C; int ldc, col0;
    if (bx < 16)      { Bh = wqh; Bl = wql; C = q; ldc = 2048; col0 = bx * 128; }
    else if (bx < 20) { Bh = wkh; Bl = wkl; C = k; ldc = 512;  col0 = (bx - 16) * 128; }
    else              { Bh = wvh; Bl = wvl; C = v; ldc = 512;  col0 = (bx - 20) * 128; }
    gemm_mma_body(xh, xl, Bh, Bl, C, ldc, blockIdx.y * 128, col0);
}

__global__ void __launch_bounds__(256, 1)
out_tc(const unsigned short* oh, const unsigned short* ol,
       const unsigned short* woh, const unsigned short* wol, float* C)
{
    gemm_mma_body(oh, ol, woh, wol, C, 2048, blockIdx.y * 128, blockIdx.x * 128);
}

// ================= rope =================
__global__ void fill_rope_table()
{
    int idx = blockIdx.x * blockDim.x + threadIdx.x;
    if (idx >= S_LEN * 64) return;
    int d = idx & 63, pos = idx >> 6;
    double inv = pow(10000.0, -((double)(2 * d)) / 128.0);
    double cd, sd;
    sincos((double)pos * inv, &sd, &cd);
    g_rope_tab[idx] = make_float2((float)cd, (float)sd);
}

__global__ void rope_apply(float* __restrict__ t, int total, int nheads)
{
    int idx = blockIdx.x * blockDim.x + threadIdx.x;
    if (idx >= total) return;
    int d = idx & 63;
    int tmp = idx >> 6;
    int h = tmp % nheads;
    int row = tmp / nheads;
    int pos = row & (S_LEN - 1);
    float2 cs = g_rope_tab[pos * 64 + d];
    float* base = t + ((size_t)row * nheads + h) * HDIM;
    float x1 = base[d], x2 = base[d + 64];
    base[d]      = x1 * cs.x - x2 * cs.y;
    base[d + 64] = x2 * cs.x + x1 * cs.y;
}

// ================= attention (causal, GQA), fp32, warp-per-4-rows =================
#define PITCH 132
__global__ void __launch_bounds__(256)
attn_simple(const float* __restrict__ Q, const float* __restrict__ K,
            const float* __restrict__ V, float* __restrict__ O)
{
    const int qt = blockIdx.x;
    const int h  = blockIdx.y;
    const int b  = blockIdx.z;
    const int g  = h >> 2;

    extern __shared__ float smf[];
    float* sQ = smf;
    float* sK = smf + 32 * PITCH;
    float* sV = smf + 2 * 32 * PITCH;

    const int tid = threadIdx.x;
    const int wid = tid >> 5;
    const int lane = tid & 31;
    const int r0 = wid * 4;

    const float* Qb = Q + ((size_t)(b * S_LEN + qt * 32)) * (NHEAD * HDIM) + h * HDIM;
    #pragma unroll
    for (int it = 0; it < 4; it++) {
        int idx = tid + it * 256;
        int r = idx >> 5;
        int seg = (idx & 31) * 4;
        *(float4*)&sQ[r * PITCH + seg] = *(const float4*)(Qb + (size_t)r * (NHEAD * HDIM) + seg);
    }

    float m[4], l[4], acc[4][4], p[4];
    #pragma unroll
    for (int i = 0; i < 4; i++) {
        m[i] = -1e30f; l[i] = 0.0f;
        acc[i][0] = acc[i][1] = acc[i][2] = acc[i][3] = 0.0f;
    }

    const int nkt = qt + 1;
    for (int kt = 0; kt < nkt; kt++) {
        __syncthreads();
        const float* Kb = K + ((size_t)(b * S_LEN + kt * 32)) * (NKVH * HDIM) + g * HDIM;
        const float* Vb = V + ((size_t)(b * S_LEN + kt * 32)) * (NKVH * HDIM) + g * HDIM;
        #pragma unroll
        for (int it = 0; it < 8; it++) {
            int idx = tid + it * 256;
            int r = (idx >> 5) & 31;
            int seg = (idx & 31) * 4;
            if (idx < 1024)
                *(float4*)&sK[r * PITCH + seg] = *(const float4*)(Kb + (size_t)r * (NKVH * HDIM) + seg);
            else
                *(float4*)&sV[r * PITCH + seg] = *(const float4*)(Vb + (size_t)r * (NKVH * HDIM) + seg);
        }
        __syncthreads();

        float s4[4] = {0.0f, 0.0f, 0.0f, 0.0f};
        #pragma unroll 8
        for (int d4 = 0; d4 < 32; d4++) {
            float4 kv = *(const float4*)&sK[lane * PITCH + d4 * 4];
            #pragma unroll
            for (int i = 0; i < 4; i++) {
                float4 qv = *(const float4*)&sQ[(r0 + i) * PITCH + d4 * 4];
                s4[i] += qv.x * kv.x + qv.y * kv.y + qv.z * kv.z + qv.w * kv.w;
            }
        }

        const int gcol = kt * 32 + lane;
        #pragma unroll
        for (int i = 0; i < 4; i++) {
            const int grow = qt * 32 + r0 + i;
            float sv = s4[i] * SCALE;
            if (gcol > grow) sv = -1e9f;
            float mx = sv;
            #pragma unroll
            for (int o = 16; o > 0; o >>= 1)
                mx = fmaxf(mx, __shfl_xor_sync(0xffffffffu, mx, o));
            float mnew = fmaxf(m[i], mx);
            float corr = __expf(m[i] - mnew);
            float pv = __expf(sv - mnew);
            float ls = pv;
            #pragma unroll
            for (int o = 16; o > 0; o >>= 1)
                ls += __shfl_xor_sync(0xffffffffu, ls, o);
            l[i] = l[i] * corr + ls;
            m[i] = mnew;
            p[i] = pv;
            acc[i][0] *= corr; acc[i][1] *= corr; acc[i][2] *= corr; acc[i][3] *= corr;
        }

        #pragma unroll 8
        for (int c = 0; c < 32; c++) {
            float4 v4 = *(const float4*)&sV[c * PITCH + lane * 4];
            #pragma unroll
            for (int i = 0; i < 4; i++) {
                float pc = __shfl_sync(0xffffffffu, p[i], c);
                acc[i][0] += pc * v4.x;
                acc[i][1] += pc * v4.y;
                acc[i][2] += pc * v4.z;
                acc[i][3] += pc * v4.w;
            }
        }
    }

    float* Ob = O + ((size_t)(b * S_LEN + qt * 32)) * (NHEAD * HDIM) + h * HDIM;
    #pragma unroll
    for (int i = 0; i < 4; i++) {
        float inv_l = 1.0f / l[i];
        *(float4*)(Ob + (size_t)(r0 + i) * (NHEAD * HDIM) + lane * 4) =
            make_float4(acc[i][0] * inv_l, acc[i][1] * inv_l, acc[i][2] * inv_l, acc[i][3] * inv_l);
    }
}

// ================= launch =================
extern "C" void kernel_launch(void* const* d_in, const int* in_sizes, int n_in,
                              void* d_out, int out_size)
{
    const float* x  = (const float*)d_in[0];
    const float* wq = (const float*)d_in[1];
    const float* wk = (const float*)d_in[2];
    const float* wv = (const float*)d_in[3];
    const float* wo = (const float*)d_in[4];
    float* out = (float*)d_out;

    float *q_p, *k_p, *v_p, *o_p;
    cudaGetSymbolAddress((void**)&q_p, g_q);
    cudaGetSymbolAddress((void**)&k_p, g_k);
    cudaGetSymbolAddress((void**)&v_p, g_v);
    cudaGetSymbolAddress((void**)&o_p, g_o);
    unsigned short *xh, *xl, *oh, *ol, *wqh, *wql, *wkh, *wkl, *wvh, *wvl, *woh, *wol;
    cudaGetSymbolAddress((void**)&xh, g_xh);   cudaGetSymbolAddress((void**)&xl, g_xl);
    cudaGetSymbolAddress((void**)&oh, g_oh);   cudaGetSymbolAddress((void**)&ol, g_ol);
    cudaGetSymbolAddress((void**)&wqh, g_wqh); cudaGetSymbolAddress((void**)&wql, g_wql);
    cudaGetSymbolAddress((void**)&wkh, g_wkh); cudaGetSymbolAddress((void**)&wkl, g_wkl);
    cudaGetSymbolAddress((void**)&wvh, g_wvh); cudaGetSymbolAddress((void**)&wvl, g_wvl);
    cudaGetSymbolAddress((void**)&woh, g_woh); cudaGetSymbolAddress((void**)&wol, g_wol);

    cudaFuncSetAttribute(qkv_tc, cudaFuncAttributeMaxDynamicSharedMemorySize, GEMM_SMEM);
    cudaFuncSetAttribute(out_tc, cudaFuncAttributeMaxDynamicSharedMemorySize, GEMM_SMEM);

    // 0. rope table + operand conversion
    fill_rope_table<<<(S_LEN * 64 + 255) / 256, 256>>>();
    {
        int tx = ROWS * HID;
        convert_split_k<<<(tx + 255) / 256, 256>>>(x, xh, xl, tx);
        transpose_split_k<<<dim3(2048 / 32, HID / 32), dim3(32, 8)>>>(wq, wqh, wql, HID, 2048);
        transpose_split_k<<<dim3(512 / 32,  HID / 32), dim3(32, 8)>>>(wk, wkh, wkl, HID, 512);
        transpose_split_k<<<dim3(512 / 32,  HID / 32), dim3(32, 8)>>>(wv, wvh, wvl, HID, 512);
        transpose_split_k<<<dim3(2048 / 32, HID / 32), dim3(32, 8)>>>(wo, woh, wol, HID, 2048);
    }

    // 1. fused QKV projections (mma.sync split-bf16)
    qkv_tc<<<dim3(24, ROWS / 128), 256, GEMM_SMEM>>>(xh, xl, wqh, wql, wkh, wkl, wvh, wvl,
                                                     q_p, k_p, v_p);

    // 2. RoPE
    {
        int tq = ROWS * NHEAD * 64;
        rope_apply<<<(tq + 255) / 256, 256>>>(q_p, tq, NHEAD);
        int tk = ROWS * NKVH * 64;
        rope_apply<<<(tk + 255) / 256, 256>>>(k_p, tk, NKVH);
    }

    // 3. attention (fp32 SIMT)
    {
        int smem = 3 * 32 * PITCH * (int)sizeof(float);
        cudaFuncSetAttribute(attn_simple, cudaFuncAttributeMaxDynamicSharedMemorySize, smem);
        attn_simple<<<dim3(S_LEN / 32, NHEAD, BATCH), 256, smem>>>(q_p, k_p, v_p, o_p);
    }

    // 4. output projection (mma.sync split-bf16)
    {
        int to = ROWS * HID;
        convert_split_k<<<(to + 255) / 256, 256>>>(o_p, oh, ol, to);
        out_tc<<<dim3(HID / 128, ROWS / 128), 256, GEMM_SMEM>>>(oh, ol, woh, wol, out);
    }
}

// round 6
// speedup vs baseline: 3.2278x; 1.7797x over previous
#include <cuda_runtime.h>
#include <cuda_bf16.h>
#include <cstdint>
#include <cstddef>

// ---------------- problem constants ----------------
#define S_LEN  2048
#define HID    2048
#define NHEAD  16
#define NKVH   4
#define HDIM   128
#define BATCH  2
#define ROWS   (BATCH * S_LEN)      // 4096
#define SCALE  0.08838834764831845f // 1/sqrt(128)

// ---------------- scratch (static device memory; no allocations) ----------------
__device__ float g_q[(size_t)ROWS * NHEAD * HDIM];
__device__ float g_k[(size_t)ROWS * NKVH  * HDIM];
__device__ float g_v[(size_t)ROWS * NKVH  * HDIM];
__device__ float2 g_rope_tab[(size_t)S_LEN * 64];

// split-bf16 operands
__device__ unsigned short g_xh[(size_t)ROWS * HID];
__device__ unsigned short g_xl[(size_t)ROWS * HID];
__device__ unsigned short g_oh[(size_t)ROWS * HID];
__device__ unsigned short g_ol[(size_t)ROWS * HID];
__device__ unsigned short g_wqh[(size_t)2048 * HID];
__device__ unsigned short g_wql[(size_t)2048 * HID];
__device__ unsigned short g_wkh[(size_t)512 * HID];
__device__ unsigned short g_wkl[(size_t)512 * HID];
__device__ unsigned short g_wvh[(size_t)512 * HID];
__device__ unsigned short g_wvl[(size_t)512 * HID];
__device__ unsigned short g_woh[(size_t)2048 * HID];
__device__ unsigned short g_wol[(size_t)2048 * HID];
// attention operands: K split (post-rope), V^T split
__device__ unsigned short g_kh[(size_t)ROWS * NKVH * HDIM];
__device__ unsigned short g_kl[(size_t)ROWS * NKVH * HDIM];
__device__ unsigned short g_vth[(size_t)BATCH * NKVH * HDIM * S_LEN];
__device__ unsigned short g_vtl[(size_t)BATCH * NKVH * HDIM * S_LEN];

// ================= mma.sync / ldmatrix helpers =================
__device__ __forceinline__ void mma_bf16(float* c, const uint32_t* a, const uint32_t* b)
{
    asm volatile(
        "mma.sync.aligned.m16n8k16.row.col.f32.bf16.bf16.f32 "
        "{%0,%1,%2,%3}, {%4,%5,%6,%7}, {%8,%9}, {%0,%1,%2,%3};"
        : "+f"(c[0]), "+f"(c[1]), "+f"(c[2]), "+f"(c[3])
        : "r"(a[0]), "r"(a[1]), "r"(a[2]), "r"(a[3]), "r"(b[0]), "r"(b[1]));
}
__device__ __forceinline__ void ldsm_x4(uint32_t* r, uint32_t addr)
{
    asm volatile("ldmatrix.sync.aligned.m8n8.x4.shared.b16 {%0,%1,%2,%3}, [%4];"
        : "=r"(r[0]), "=r"(r[1]), "=r"(r[2]), "=r"(r[3]) : "r"(addr));
}
__device__ __forceinline__ uint32_t smem_u32(const void* p) {
    uint32_t a;
    asm("{ .reg .u64 t; cvta.to.shared.u64 t, %1; cvt.u32.u64 %0, t; }" : "=r"(a) : "l"(p));
    return a;
}
__device__ __forceinline__ unsigned short f2bf(float v) {
    __nv_bfloat16 b = __float2bfloat16(v);
    return *(unsigned short*)&b;
}
__device__ __forceinline__ float bf2f(unsigned short u) {
    __nv_bfloat16 b = *(__nv_bfloat16*)&u;
    return __bfloat162float(b);
}
// split v into hi/lo bf16; returns packed halves for (a, b) pair
__device__ __forceinline__ void split_pack(float a, float b, uint32_t& h, uint32_t& l)
{
    unsigned short ah = f2bf(a), bh = f2bf(b);
    unsigned short al = f2bf(a - bf2f(ah)), bl = f2bf(b - bf2f(bh));
    h = (uint32_t)ah | ((uint32_t)bh << 16);
    l = (uint32_t)al | ((uint32_t)bl << 16);
}

// ================= conversion kernels =================
__device__ __forceinline__ void bf16_split(float v, unsigned short& h, unsigned short& l) {
    __nv_bfloat16 hb = __float2bfloat16(v);
    __nv_bfloat16 lb = __float2bfloat16(v - __bfloat162float(hb));
    h = *(unsigned short*)&hb;
    l = *(unsigned short*)&lb;
}

__global__ void convert_split_k(const float* __restrict__ src,
                                unsigned short* __restrict__ hi,
                                unsigned short* __restrict__ lo, int total)
{
    int i = blockIdx.x * blockDim.x + threadIdx.x;
    if (i >= total) return;
    bf16_split(src[i], hi[i], lo[i]);
}

// src [K][N] fp32 -> hi/lo [N][K] bf16 (transpose + split)
__global__ void transpose_split_k(const float* __restrict__ src,
                                  unsigned short* __restrict__ hi,
                                  unsigned short* __restrict__ lo, int K, int N)
{
    __shared__ float t[32][33];
    const int n0 = blockIdx.x * 32, k0 = blockIdx.y * 32;
    const int tx = threadIdx.x, ty = threadIdx.y; // (32, 8)
    #pragma unroll
    for (int i = 0; i < 4; i++)
        t[ty + i * 8][tx] = src[(size_t)(k0 + ty + i * 8) * N + n0 + tx];
    __syncthreads();
    #pragma unroll
    for (int i = 0; i < 4; i++) {
        int n = ty + i * 8;
        float v = t[tx][n];
        unsigned short h, l;
        bf16_split(v, h, l);
        size_t o = (size_t)(n0 + n) * K + k0 + tx;
        hi[o] = h; lo[o] = l;
    }
}

// V [(b*S+key)*4+g][128] fp32 -> vth/vtl [bg][d][2048] (transpose + split)
__global__ void vt_split(const float* __restrict__ v,
                         unsigned short* __restrict__ vth,
                         unsigned short* __restrict__ vtl)
{
    __shared__ float t[32][33];    // [key_local][d_local]
    const int bg = blockIdx.z;
    const int b = bg >> 2, g = bg & 3;
    const int key0 = blockIdx.x * 32, d0 = blockIdx.y * 32;
    const int tx = threadIdx.x, ty = threadIdx.y; // (32, 8)
    #pragma unroll
    for (int i = 0; i < 4; i++)
        t[ty + i * 8][tx] = v[((size_t)(b * S_LEN + key0 + ty + i * 8) * 4 + g) * 128 + d0 + tx];
    __syncthreads();
    #pragma unroll
    for (int i = 0; i < 4; i++) {
        int dl = ty + i * 8;
        float val = t[tx][dl];
        unsigned short h, l;
        bf16_split(val, h, l);
        size_t o = ((size_t)bg * 128 + d0 + dl) * S_LEN + key0 + tx;
        vth[o] = h; vtl[o] = l;
    }
}

// ================= split-bf16 GEMM via mma.sync (unchanged from R5) =================
#define KTILE    32
#define NT_STEPS (HID / KTILE)
#define APITCH   40
#define TILE_U16 (128 * APITCH)
#define BUF_U16  (4 * TILE_U16)
#define GEMM_SMEM (2 * BUF_U16 * 2)

__device__ void gemm_mma_body(const unsigned short* __restrict__ Ah, const unsigned short* __restrict__ Al,
                              const unsigned short* __restrict__ Bh, const unsigned short* __restrict__ Bl,
                              float* __restrict__ C, int ldc, int row0, int col0)
{
    extern __shared__ unsigned short sm[];
    const int tid  = threadIdx.x;
    const int wid  = tid >> 5;
    const int lane = tid & 31;
    const int wm   = wid & 1;
    const int wn   = wid >> 1;
    const int g    = lane >> 2;
    const int tq   = lane & 3;

    const int r    = tid >> 1;
    const int half = tid & 1;
    const unsigned short* pAh = Ah + (size_t)(row0 + r) * HID + half * 16;
    const unsigned short* pAl = Al + (size_t)(row0 + r) * HID + half * 16;
    const unsigned short* pBh = Bh + (size_t)(col0 + r) * HID + half * 16;
    const unsigned short* pBl = Bl + (size_t)(col0 + r) * HID + half * 16;
    const uint32_t soff = (uint32_t)(r * APITCH + half * 16);

    float acc[4][4][4];
    #pragma unroll
    for (int mi = 0; mi < 4; mi++)
        #pragma unroll
        for (int ni = 0; ni < 4; ni++)
            #pragma unroll
            for (int e = 0; e < 4; e++) acc[mi][ni][e] = 0.0f;

    {
        unsigned short* b0 = sm;
        *(uint4*)(b0 + soff)                 = *(const uint4*)(pAh);
        *(uint4*)(b0 + soff + 8)             = *(const uint4*)(pAh + 8);
        *(uint4*)(b0 + TILE_U16 + soff)      = *(const uint4*)(pAl);
        *(uint4*)(b0 + TILE_U16 + soff + 8)  = *(const uint4*)(pAl + 8);
        *(uint4*)(b0 + 2*TILE_U16 + soff)    = *(const uint4*)(pBh);
        *(uint4*)(b0 + 2*TILE_U16 + soff + 8)= *(const uint4*)(pBh + 8);
        *(uint4*)(b0 + 3*TILE_U16 + soff)    = *(const uint4*)(pBl);
        *(uint4*)(b0 + 3*TILE_U16 + soff + 8)= *(const uint4*)(pBl + 8);
    }
    __syncthreads();

    for (int t = 0; t < NT_STEPS; t++) {
        const int cur = t & 1;
        const bool has_next = (t + 1) < NT_STEPS;
        uint4 nAh0, nAh1, nAl0, nAl1, nBh0, nBh1, nBl0, nBl1;
        if (has_next) {
            const int kn = (t + 1) * KTILE;
            nAh0 = *(const uint4*)(pAh + kn); nAh1 = *(const uint4*)(pAh + kn + 8);
            nAl0 = *(const uint4*)(pAl + kn); nAl1 = *(const uint4*)(pAl + kn + 8);
            nBh0 = *(const uint4*)(pBh + kn); nBh1 = *(const uint4*)(pBh + kn + 8);
            nBl0 = *(const uint4*)(pBl + kn); nBl1 = *(const uint4*)(pBl + kn + 8);
        }

        const unsigned short* sa_h = sm + cur * BUF_U16;
        const unsigned short* sa_l = sa_h + TILE_U16;
        const unsigned short* sb_h = sa_h + 2 * TILE_U16;
        const unsigned short* sb_l = sa_h + 3 * TILE_U16;

        #pragma unroll
        for (int ks = 0; ks < KTILE; ks += 16) {
            uint32_t ah[4][4], al[4][4], bh[4][2], bl[4][2];
            #pragma unroll
            for (int mi = 0; mi < 4; mi++) {
                const int arow = (wm * 64 + mi * 16 + g) * APITCH + ks + tq * 2;
                ah[mi][0] = *(const uint32_t*)(sa_h + arow);
                ah[mi][1] = *(const uint32_t*)(sa_h + arow + 8 * APITCH);
                ah[mi][2] = *(const uint32_t*)(sa_h + arow + 8);
                ah[mi][3] = *(const uint32_t*)(sa_h + arow + 8 * APITCH + 8);
                al[mi][0] = *(const uint32_t*)(sa_l + arow);
                al[mi][1] = *(const uint32_t*)(sa_l + arow + 8 * APITCH);
                al[mi][2] = *(const uint32_t*)(sa_l + arow + 8);
                al[mi][3] = *(const uint32_t*)(sa_l + arow + 8 * APITCH + 8);
            }
            #pragma unroll
            for (int ni = 0; ni < 4; ni++) {
                const int brow = (wn * 32 + ni * 8 + g) * APITCH + ks + tq * 2;
                bh[ni][0] = *(const uint32_t*)(sb_h + brow);
                bh[ni][1] = *(const uint32_t*)(sb_h + brow + 8);
                bl[ni][0] = *(const uint32_t*)(sb_l + brow);
                bl[ni][1] = *(const uint32_t*)(sb_l + brow + 8);
            }
            #pragma unroll
            for (int mi = 0; mi < 4; mi++)
                #pragma unroll
                for (int ni = 0; ni < 4; ni++) {
                    mma_bf16(acc[mi][ni], ah[mi], bh[ni]);
                    mma_bf16(acc[mi][ni], ah[mi], bl[ni]);
                    mma_bf16(acc[mi][ni], al[mi], bh[ni]);
                }
        }

        if (has_next) {
            unsigned short* bn = sm + (cur ^ 1) * BUF_U16;
            *(uint4*)(bn + soff)                  = nAh0;
            *(uint4*)(bn + soff + 8)              = nAh1;
            *(uint4*)(bn + TILE_U16 + soff)       = nAl0;
            *(uint4*)(bn + TILE_U16 + soff + 8)   = nAl1;
            *(uint4*)(bn + 2*TILE_U16 + soff)     = nBh0;
            *(uint4*)(bn + 2*TILE_U16 + soff + 8) = nBh1;
            *(uint4*)(bn + 3*TILE_U16 + soff)     = nBl0;
            *(uint4*)(bn + 3*TILE_U16 + soff + 8) = nBl1;
        }
        __syncthreads();
    }

    #pragma unroll
    for (int mi = 0; mi < 4; mi++) {
        const int mrow = row0 + wm * 64 + mi * 16 + g;
        #pragma unroll
        for (int ni = 0; ni < 4; ni++) {
            const int ncol = col0 + wn * 32 + ni * 8 + tq * 2;
            *(float2*)(C + (size_t)mrow * ldc + ncol)       = make_float2(acc[mi][ni][0], acc[mi][ni][1]);
            *(float2*)(C + (size_t)(mrow + 8) * ldc + ncol) = make_float2(acc[mi][ni][2], acc[mi][ni][3]);
        }
    }
}

__global__ void __launch_bounds__(256, 1)
qkv_tc(const unsigned short* xh, const unsigned short* xl,
       const unsigned short* wqh, const unsigned short* wql,
       const unsigned short* wkh, const unsigned short* wkl,
       const unsigned short* wvh, const unsigned short* wvl,
       float* q, float* k, float* v)
{
    const int bx = blockIdx.x;
    const unsigned short *Bh, *Bl; float* C; int ldc, col0;
    if (bx < 16)      { Bh = wqh; Bl = wql; C = q; ldc = 2048; col0 = bx * 128; }
    else if (bx < 20) { Bh = wkh; Bl = wkl; C = k; ldc = 512;  col0 = (bx - 16) * 128; }
    else              { Bh = wvh; Bl = wvl; C = v; ldc = 512;  col0 = (bx - 20) * 128; }
    gemm_mma_body(xh, xl, Bh, Bl, C, ldc, blockIdx.y * 128, col0);
}

__global__ void __launch_bounds__(256, 1)
out_tc(const unsigned short* oh, const unsigned short* ol,
       const unsigned short* woh, const unsigned short* wol, float* C)
{
    gemm_mma_body(oh, ol, woh, wol, C, 2048, blockIdx.y * 128, blockIdx.x * 128);
}

// ================= rope =================
__global__ void fill_rope_table()
{
    int idx = blockIdx.x * blockDim.x + threadIdx.x;
    if (idx >= S_LEN * 64) return;
    int d = idx & 63, pos = idx >> 6;
    double inv = pow(10000.0, -((double)(2 * d)) / 128.0);
    double cd, sd;
    sincos((double)pos * inv, &sd, &cd);
    g_rope_tab[idx] = make_float2((float)cd, (float)sd);
}

__global__ void rope_apply(float* __restrict__ t, int total, int nheads)
{
    int idx = blockIdx.x * blockDim.x + threadIdx.x;
    if (idx >= total) return;
    int d = idx & 63;
    int tmp = idx >> 6;
    int h = tmp % nheads;
    int row = tmp / nheads;
    int pos = row & (S_LEN - 1);
    float2 cs = g_rope_tab[pos * 64 + d];
    float* base = t + ((size_t)row * nheads + h) * HDIM;
    float x1 = base[d], x2 = base[d + 64];
    base[d]      = x1 * cs.x - x2 * cs.y;
    base[d + 64] = x2 * cs.x + x1 * cs.y;
}

// ================= flash attention via mma.sync, split-bf16 =================
// grid (S/64, NH, B); block 128 (4 warps); warp owns 16 q rows; kv tile 64 keys.
#define AKP 136     // K smem pitch (u16): 272B, LDSM conflict-free
#define AVP 72      // V^T smem pitch (u16): 144B
#define SKH 0
#define SKL (64 * AKP)
#define SVH (2 * 64 * AKP)
#define SVL (2 * 64 * AKP + 128 * AVP)
#define ATT_SMEM ((2 * 64 * AKP + 2 * 128 * AVP) * 2)   // 71680 B

__global__ void __launch_bounds__(128)
attn_mma(const float* __restrict__ Q,
         const unsigned short* __restrict__ Kh, const unsigned short* __restrict__ Kl,
         const unsigned short* __restrict__ Vth, const unsigned short* __restrict__ Vtl,
         unsigned short* __restrict__ Oh, unsigned short* __restrict__ Ol)
{
    const int qt = blockIdx.x;     // 0..31 (64 q rows per block)
    const int h  = blockIdx.y;
    const int b  = blockIdx.z;
    const int g4 = h >> 2;         // kv group
    const int bg = b * 4 + g4;

    extern __shared__ unsigned short smu[];
    const uint32_t sbase = smem_u32(smu);

    const int tid  = threadIdx.x;
    const int wid  = tid >> 5;
    const int lane = tid & 31;
    const int gr   = lane >> 2;    // 0..7 (row within fragment)
    const int tq   = lane & 3;

    // per-thread LDSM address components
    const int lr    = lane & 7;
    const int off8a = (lane & 8)  ? 8 : 0;   // matrix bit0
    const int off8b = (lane & 16) ? 8 : 0;   // matrix bit1

    // ---- load Q fragments (rows rA=q0+gr, rB=q0+gr+8), scale + split ----
    const int q0 = qt * 64 + wid * 16;
    const float* pq0 = Q + ((size_t)(b * S_LEN + q0 + gr) * 16 + h) * 128;
    const float* pq1 = Q + ((size_t)(b * S_LEN + q0 + gr + 8) * 16 + h) * 128;
    uint32_t qh[8][4], ql[8][4];
    #pragma unroll
    for (int ks = 0; ks < 8; ks++) {
        float2 x0 = *(const float2*)(pq0 + 16 * ks + 2 * tq);
        float2 x1 = *(const float2*)(pq1 + 16 * ks + 2 * tq);
        float2 x2 = *(const float2*)(pq0 + 16 * ks + 2 * tq + 8);
        float2 x3 = *(const float2*)(pq1 + 16 * ks + 2 * tq + 8);
        split_pack(x0.x * SCALE, x0.y * SCALE, qh[ks][0], ql[ks][0]);
        split_pack(x1.x * SCALE, x1.y * SCALE, qh[ks][1], ql[ks][1]);
        split_pack(x2.x * SCALE, x2.y * SCALE, qh[ks][2], ql[ks][2]);
        split_pack(x3.x * SCALE, x3.y * SCALE, qh[ks][3], ql[ks][3]);
    }

    float o[16][4];
    #pragma unroll
    for (int j = 0; j < 16; j++)
        #pragma unroll
        for (int e = 0; e < 4; e++) o[j][e] = 0.0f;
    float m0 = -1e30f, m1 = -1e30f, l0 = 0.0f, l1 = 0.0f;

    const unsigned short* kh_base = Kh + ((size_t)(b * S_LEN) * 4 + g4) * 128;
    const unsigned short* kl_base = Kl + ((size_t)(b * S_LEN) * 4 + g4) * 128;
    const unsigned short* vth_base = Vth + (size_t)bg * 128 * S_LEN;
    const unsigned short* vtl_base = Vtl + (size_t)bg * 128 * S_LEN;

    for (int kt = 0; kt <= qt; kt++) {
        __syncthreads();
        // ---- load K tile (64 keys x 128 d, hi+lo) ----
        {
            const unsigned short* src_h = kh_base + (size_t)(kt * 64) * 512;
            const unsigned short* src_l = kl_base + (size_t)(kt * 64) * 512;
            #pragma unroll
            for (int i = 0; i < 8; i++) {
                int idx = tid + i * 128;           // 0..1023
                int row = idx >> 4, seg = (idx & 15) * 8;
                *(uint4*)(smu + SKH + row * AKP + seg) = *(const uint4*)(src_h + (size_t)row * 512 + seg);
                *(uint4*)(smu + SKL + row * AKP + seg) = *(const uint4*)(src_l + (size_t)row * 512 + seg);
            }
            const unsigned short* sv_h = vth_base + kt * 64;
            const unsigned short* sv_l = vtl_base + kt * 64;
            #pragma unroll
            for (int i = 0; i < 8; i++) {
                int idx = tid + i * 128;
                int row = idx >> 3, seg = (idx & 7) * 8;
                *(uint4*)(smu + SVH + row * AVP + seg) = *(const uint4*)(sv_h + (size_t)row * S_LEN + seg);
                *(uint4*)(smu + SVL + row * AVP + seg) = *(const uint4*)(sv_l + (size_t)row * S_LEN + seg);
            }
        }
        __syncthreads();

        // ---- scores: s[j] (j = key-frag 0..7), 3-term split mma ----
        float s[8][4];
        #pragma unroll
        for (int j = 0; j < 8; j++)
            #pragma unroll
            for (int e = 0; e < 4; e++) s[j][e] = 0.0f;

        #pragma unroll
        for (int jj = 0; jj < 4; jj++) {
            #pragma unroll
            for (int ks = 0; ks < 8; ks++) {
                uint32_t bh[4], bl[4];
                uint32_t a_h = sbase + 2 * (uint32_t)(SKH + (16 * jj + off8b + lr) * AKP + 16 * ks + off8a);
                uint32_t a_l = sbase + 2 * (uint32_t)(SKL + (16 * jj + off8b + lr) * AKP + 16 * ks + off8a);
                ldsm_x4(bh, a_h);
                ldsm_x4(bl, a_l);
                mma_bf16(s[2*jj],   qh[ks], bh + 0);
                mma_bf16(s[2*jj],   qh[ks], bl + 0);
                mma_bf16(s[2*jj],   ql[ks], bh + 0);
                mma_bf16(s[2*jj+1], qh[ks], bh + 2);
                mma_bf16(s[2*jj+1], qh[ks], bl + 2);
                mma_bf16(s[2*jj+1], ql[ks], bh + 2);
            }
        }

        // ---- causal mask on diagonal tile ----
        if (kt == qt) {
            const int rl0 = wid * 16 + gr;
            const int rl1 = rl0 + 8;
            #pragma unroll
            for (int j = 0; j < 8; j++) {
                int c0 = 8 * j + 2 * tq, c1 = c0 + 1;
                if (c0 > rl0) s[j][0] = -1e30f;
                if (c1 > rl0) s[j][1] = -1e30f;
                if (c0 > rl1) s[j][2] = -1e30f;
                if (c1 > rl1) s[j][3] = -1e30f;
            }
        }

        // ---- online softmax (rows gr and gr+8 of this warp) ----
        float mx0 = -1e30f, mx1 = -1e30f;
        #pragma unroll
        for (int j = 0; j < 8; j++) {
            mx0 = fmaxf(mx0, fmaxf(s[j][0], s[j][1]));
            mx1 = fmaxf(mx1, fmaxf(s[j][2], s[j][3]));
        }
        mx0 = fmaxf(mx0, __shfl_xor_sync(0xffffffffu, mx0, 1));
        mx0 = fmaxf(mx0, __shfl_xor_sync(0xffffffffu, mx0, 2));
        mx1 = fmaxf(mx1, __shfl_xor_sync(0xffffffffu, mx1, 1));
        mx1 = fmaxf(mx1, __shfl_xor_sync(0xffffffffu, mx1, 2));

        float mn0 = fmaxf(m0, mx0), mn1 = fmaxf(m1, mx1);
        float c0 = __expf(m0 - mn0), c1 = __expf(m1 - mn1);

        uint32_t ph[8][2], pl[8][2];
        float sum0 = 0.0f, sum1 = 0.0f;
        #pragma unroll
        for (int j = 0; j < 8; j++) {
            float p0 = __expf(s[j][0] - mn0);
            float p1 = __expf(s[j][1] - mn0);
            float p2 = __expf(s[j][2] - mn1);
            float p3 = __expf(s[j][3] - mn1);
            sum0 += p0 + p1;
            sum1 += p2 + p3;
            split_pack(p0, p1, ph[j][0], pl[j][0]);
            split_pack(p2, p3, ph[j][1], pl[j][1]);
        }
        sum0 += __shfl_xor_sync(0xffffffffu, sum0, 1);
        sum0 += __shfl_xor_sync(0xffffffffu, sum0, 2);
        sum1 += __shfl_xor_sync(0xffffffffu, sum1, 1);
        sum1 += __shfl_xor_sync(0xffffffffu, sum1, 2);
        l0 = l0 * c0 + sum0;
        l1 = l1 * c1 + sum1;
        m0 = mn0; m1 = mn1;
        #pragma unroll
        for (int j = 0; j < 16; j++) {
            o[j][0] *= c0; o[j][1] *= c0;
            o[j][2] *= c1; o[j][3] *= c1;
        }

        // ---- PV: o[n-frag] += P x V^T frags, 3-term split ----
        #pragma unroll
        for (int ks = 0; ks < 4; ks++) {
            uint32_t ah4[4] = { ph[2*ks][0], ph[2*ks][1], ph[2*ks+1][0], ph[2*ks+1][1] };
            uint32_t al4[4] = { pl[2*ks][0], pl[2*ks][1], pl[2*ks+1][0], pl[2*ks+1][1] };
            #pragma unroll
            for (int jj = 0; jj < 8; jj++) {
                uint32_t bh[4], bl[4];
                uint32_t a_h = sbase + 2 * (uint32_t)(SVH + (16 * jj + off8b + lr) * AVP + 16 * ks + off8a);
                uint32_t a_l = sbase + 2 * (uint32_t)(SVL + (16 * jj + off8b + lr) * AVP + 16 * ks + off8a);
                ldsm_x4(bh, a_h);
                ldsm_x4(bl, a_l);
                mma_bf16(o[2*jj],   ah4, bh + 0);
                mma_bf16(o[2*jj],   ah4, bl + 0);
                mma_bf16(o[2*jj],   al4, bh + 0);
                mma_bf16(o[2*jj+1], ah4, bh + 2);
                mma_bf16(o[2*jj+1], ah4, bl + 2);
                mma_bf16(o[2*jj+1], al4, bh + 2);
            }
        }
    }

    // ---- epilogue: normalize, split to bf16 hi/lo, store ----
    const float inv0 = 1.0f / l0, inv1 = 1.0f / l1;
    const size_t rowA = (size_t)(b * S_LEN + q0 + gr) * 2048 + h * 128;
    const size_t rowB = (size_t)(b * S_LEN + q0 + gr + 8) * 2048 + h * 128;
    #pragma unroll
    for (int j = 0; j < 16; j++) {
        const int col = 8 * j + 2 * tq;
        uint32_t h0, l0r, h1, l1r;
        split_pack(o[j][0] * inv0, o[j][1] * inv0, h0, l0r);
        split_pack(o[j][2] * inv1, o[j][3] * inv1, h1, l1r);
        *(uint32_t*)(Oh + rowA + col) = h0;
        *(uint32_t*)(Ol + rowA + col) = l0r;
        *(uint32_t*)(Oh + rowB + col) = h1;
        *(uint32_t*)(Ol + rowB + col) = l1r;
    }
}

// ================= launch =================
extern "C" void kernel_launch(void* const* d_in, const int* in_sizes, int n_in,
                              void* d_out, int out_size)
{
    const float* x  = (const float*)d_in[0];
    const float* wq = (const float*)d_in[1];
    const float* wk = (const float*)d_in[2];
    const float* wv = (const float*)d_in[3];
    const float* wo = (const float*)d_in[4];
    float* out = (float*)d_out;

    float *q_p, *k_p, *v_p;
    cudaGetSymbolAddress((void**)&q_p, g_q);
    cudaGetSymbolAddress((void**)&k_p, g_k);
    cudaGetSymbolAddress((void**)&v_p, g_v);
    unsigned short *xh, *xl, *oh, *ol, *wqh, *wql, *wkh, *wkl, *wvh, *wvl, *woh, *wol;
    unsigned short *kh, *kl, *vth, *vtl;
    cudaGetSymbolAddress((void**)&xh, g_xh);   cudaGetSymbolAddress((void**)&xl, g_xl);
    cudaGetSymbolAddress((void**)&oh, g_oh);   cudaGetSymbolAddress((void**)&ol, g_ol);
    cudaGetSymbolAddress((void**)&wqh, g_wqh); cudaGetSymbolAddress((void**)&wql, g_wql);
    cudaGetSymbolAddress((void**)&wkh, g_wkh); cudaGetSymbolAddress((void**)&wkl, g_wkl);
    cudaGetSymbolAddress((void**)&wvh, g_wvh); cudaGetSymbolAddress((void**)&wvl, g_wvl);
    cudaGetSymbolAddress((void**)&woh, g_woh); cudaGetSymbolAddress((void**)&wol, g_wol);
    cudaGetSymbolAddress((void**)&kh, g_kh);   cudaGetSymbolAddress((void**)&kl, g_kl);
    cudaGetSymbolAddress((void**)&vth, g_vth); cudaGetSymbolAddress((void**)&vtl, g_vtl);

    cudaFuncSetAttribute(qkv_tc, cudaFuncAttributeMaxDynamicSharedMemorySize, GEMM_SMEM);
    cudaFuncSetAttribute(out_tc, cudaFuncAttributeMaxDynamicSharedMemorySize, GEMM_SMEM);
    cudaFuncSetAttribute(attn_mma, cudaFuncAttributeMaxDynamicSharedMemorySize, ATT_SMEM);

    // 0. rope table + operand conversion
    fill_rope_table<<<(S_LEN * 64 + 255) / 256, 256>>>();
    {
        int tx = ROWS * HID;
        convert_split_k<<<(tx + 255) / 256, 256>>>(x, xh, xl, tx);
        transpose_split_k<<<dim3(2048 / 32, HID / 32), dim3(32, 8)>>>(wq, wqh, wql, HID, 2048);
        transpose_split_k<<<dim3(512 / 32,  HID / 32), dim3(32, 8)>>>(wk, wkh, wkl, HID, 512);
        transpose_split_k<<<dim3(512 / 32,  HID / 32), dim3(32, 8)>>>(wv, wvh, wvl, HID, 512);
        transpose_split_k<<<dim3(2048 / 32, HID / 32), dim3(32, 8)>>>(wo, woh, wol, HID, 2048);
    }

    // 1. fused QKV projections
    qkv_tc<<<dim3(24, ROWS / 128), 256, GEMM_SMEM>>>(xh, xl, wqh, wql, wkh, wkl, wvh, wvl,
                                                     q_p, k_p, v_p);

    // 2. RoPE on q, k; then split K; transpose+split V
    {
        int tq = ROWS * NHEAD * 64;
        rope_apply<<<(tq + 255) / 256, 256>>>(q_p, tq, NHEAD);
        int tk = ROWS * NKVH * 64;
        rope_apply<<<(tk + 255) / 256, 256>>>(k_p, tk, NKVH);
        int tke = ROWS * NKVH * HDIM;
        convert_split_k<<<(tke + 255) / 256, 256>>>(k_p, kh, kl, tke);
        vt_split<<<dim3(S_LEN / 32, HDIM / 32, BATCH * NKVH), dim3(32, 8)>>>(v_p, vth, vtl);
    }

    // 3. flash attention (mma.sync split-bf16); writes oh/ol directly
    attn_mma<<<dim3(S_LEN / 64, NHEAD, BATCH), 128, ATT_SMEM>>>(q_p, kh, kl, vth, vtl, oh, ol);

    // 4. output projection
    out_tc<<<dim3(HID / 128, ROWS / 128), 256, GEMM_SMEM>>>(oh, ol, woh, wol, out);
}

// round 7
// speedup vs baseline: 3.5656x; 1.1047x over previous
#include <cuda_runtime.h>
#include <cuda_bf16.h>
#include <cstdint>
#include <cstddef>

// ---------------- problem constants ----------------
#define S_LEN  2048
#define HID    2048
#define NHEAD  16
#define NKVH   4
#define HDIM   128
#define BATCH  2
#define ROWS   (BATCH * S_LEN)      // 4096
#define SCALE  0.08838834764831845f // 1/sqrt(128)

// ---------------- scratch (static device memory; no allocations) ----------------
__device__ float g_q[(size_t)ROWS * NHEAD * HDIM];
__device__ float g_k[(size_t)ROWS * NKVH  * HDIM];
__device__ float g_v[(size_t)ROWS * NKVH  * HDIM];
__device__ float2 g_rope_tab[(size_t)S_LEN * 64];

// split-bf16 operands
__device__ unsigned short g_xh[(size_t)ROWS * HID];
__device__ unsigned short g_xl[(size_t)ROWS * HID];
__device__ unsigned short g_oh[(size_t)ROWS * HID];
__device__ unsigned short g_ol[(size_t)ROWS * HID];
__device__ unsigned short g_wqh[(size_t)2048 * HID];
__device__ unsigned short g_wql[(size_t)2048 * HID];
__device__ unsigned short g_wkh[(size_t)512 * HID];
__device__ unsigned short g_wkl[(size_t)512 * HID];
__device__ unsigned short g_wvh[(size_t)512 * HID];
__device__ unsigned short g_wvl[(size_t)512 * HID];
__device__ unsigned short g_woh[(size_t)2048 * HID];
__device__ unsigned short g_wol[(size_t)2048 * HID];
// attention operands: K split (post-rope), V^T split
__device__ unsigned short g_kh[(size_t)ROWS * NKVH * HDIM];
__device__ unsigned short g_kl[(size_t)ROWS * NKVH * HDIM];
__device__ unsigned short g_vth[(size_t)BATCH * NKVH * HDIM * S_LEN];
__device__ unsigned short g_vtl[(size_t)BATCH * NKVH * HDIM * S_LEN];

// ================= mma.sync / ldmatrix helpers =================
__device__ __forceinline__ void mma_bf16(float* c, const uint32_t* a, const uint32_t* b)
{
    asm volatile(
        "mma.sync.aligned.m16n8k16.row.col.f32.bf16.bf16.f32 "
        "{%0,%1,%2,%3}, {%4,%5,%6,%7}, {%8,%9}, {%0,%1,%2,%3};"
        : "+f"(c[0]), "+f"(c[1]), "+f"(c[2]), "+f"(c[3])
        : "r"(a[0]), "r"(a[1]), "r"(a[2]), "r"(a[3]), "r"(b[0]), "r"(b[1]));
}
__device__ __forceinline__ void ldsm_x4(uint32_t* r, uint32_t addr)
{
    asm volatile("ldmatrix.sync.aligned.m8n8.x4.shared.b16 {%0,%1,%2,%3}, [%4];"
        : "=r"(r[0]), "=r"(r[1]), "=r"(r[2]), "=r"(r[3]) : "r"(addr));
}
__device__ __forceinline__ uint32_t smem_u32(const void* p) {
    uint32_t a;
    asm("{ .reg .u64 t; cvta.to.shared.u64 t, %1; cvt.u32.u64 %0, t; }" : "=r"(a) : "l"(p));
    return a;
}
__device__ __forceinline__ unsigned short f2bf(float v) {
    __nv_bfloat16 b = __float2bfloat16(v);
    return *(unsigned short*)&b;
}
__device__ __forceinline__ float bf2f(unsigned short u) {
    __nv_bfloat16 b = *(__nv_bfloat16*)&u;
    return __bfloat162float(b);
}
__device__ __forceinline__ void split_pack(float a, float b, uint32_t& h, uint32_t& l)
{
    unsigned short ah = f2bf(a), bh = f2bf(b);
    unsigned short al = f2bf(a - bf2f(ah)), bl = f2bf(b - bf2f(bh));
    h = (uint32_t)ah | ((uint32_t)bh << 16);
    l = (uint32_t)al | ((uint32_t)bl << 16);
}

// ================= conversion kernels =================
__device__ __forceinline__ void bf16_split(float v, unsigned short& h, unsigned short& l) {
    __nv_bfloat16 hb = __float2bfloat16(v);
    __nv_bfloat16 lb = __float2bfloat16(v - __bfloat162float(hb));
    h = *(unsigned short*)&hb;
    l = *(unsigned short*)&lb;
}

__global__ void convert_split_k(const float* __restrict__ src,
                                unsigned short* __restrict__ hi,
                                unsigned short* __restrict__ lo, int total)
{
    int i = blockIdx.x * blockDim.x + threadIdx.x;
    if (i >= total) return;
    bf16_split(src[i], hi[i], lo[i]);
}

// src [K][N] fp32 -> hi/lo [N][K] bf16 (transpose + split)
__global__ void transpose_split_k(const float* __restrict__ src,
                                  unsigned short* __restrict__ hi,
                                  unsigned short* __restrict__ lo, int K, int N)
{
    __shared__ float t[32][33];
    const int n0 = blockIdx.x * 32, k0 = blockIdx.y * 32;
    const int tx = threadIdx.x, ty = threadIdx.y; // (32, 8)
    #pragma unroll
    for (int i = 0; i < 4; i++)
        t[ty + i * 8][tx] = src[(size_t)(k0 + ty + i * 8) * N + n0 + tx];
    __syncthreads();
    #pragma unroll
    for (int i = 0; i < 4; i++) {
        int n = ty + i * 8;
        float v = t[tx][n];
        unsigned short h, l;
        bf16_split(v, h, l);
        size_t o = (size_t)(n0 + n) * K + k0 + tx;
        hi[o] = h; lo[o] = l;
    }
}

// V [(b*S+key)*4+g][128] fp32 -> vth/vtl [bg][d][2048] (transpose + split)
__global__ void vt_split(const float* __restrict__ v,
                         unsigned short* __restrict__ vth,
                         unsigned short* __restrict__ vtl)
{
    __shared__ float t[32][33];    // [key_local][d_local]
    const int bg = blockIdx.z;
    const int b = bg >> 2, g = bg & 3;
    const int key0 = blockIdx.x * 32, d0 = blockIdx.y * 32;
    const int tx = threadIdx.x, ty = threadIdx.y; // (32, 8)
    #pragma unroll
    for (int i = 0; i < 4; i++)
        t[ty + i * 8][tx] = v[((size_t)(b * S_LEN + key0 + ty + i * 8) * 4 + g) * 128 + d0 + tx];
    __syncthreads();
    #pragma unroll
    for (int i = 0; i < 4; i++) {
        int dl = ty + i * 8;
        float val = t[tx][dl];
        unsigned short h, l;
        bf16_split(val, h, l);
        size_t o = ((size_t)bg * 128 + d0 + dl) * S_LEN + key0 + tx;
        vth[o] = h; vtl[o] = l;
    }
}

// ================= split-bf16 GEMM via mma.sync + ldmatrix =================
#define KTILE    32
#define NT_STEPS (HID / KTILE)
#define APITCH   40
#define TILE_U16 (128 * APITCH)
#define BUF_U16  (4 * TILE_U16)
#define GEMM_SMEM (2 * BUF_U16 * 2)

__device__ void gemm_mma_body(const unsigned short* __restrict__ Ah, const unsigned short* __restrict__ Al,
                              const unsigned short* __restrict__ Bh, const unsigned short* __restrict__ Bl,
                              float* __restrict__ C, int ldc, int row0, int col0)
{
    extern __shared__ unsigned short sm[];
    const uint32_t sbase = smem_u32(sm);
    const int tid  = threadIdx.x;
    const int wid  = tid >> 5;
    const int lane = tid & 31;
    const int wm   = wid & 1;
    const int wn   = wid >> 1;
    const int g    = lane >> 2;
    const int tq   = lane & 3;

    // ldmatrix per-thread address components
    const int lr   = lane & 7;
    const int oaR  = (lane & 8)  ? 8 : 0;   // A: row offset
    const int oaC  = (lane & 16) ? 8 : 0;   // A: col offset
    const int obR  = (lane & 16) ? 8 : 0;   // B: row offset
    const int obC  = (lane & 8)  ? 8 : 0;   // B: col offset
    const int rowA0 = wm * 64 + lr + oaR;   // + mi*16
    const int rowB0 = wn * 32 + lr + obR;   // + jj*16

    const int r    = tid >> 1;
    const int half = tid & 1;
    const unsigned short* pAh = Ah + (size_t)(row0 + r) * HID + half * 16;
    const unsigned short* pAl = Al + (size_t)(row0 + r) * HID + half * 16;
    const unsigned short* pBh = Bh + (size_t)(col0 + r) * HID + half * 16;
    const unsigned short* pBl = Bl + (size_t)(col0 + r) * HID + half * 16;
    const uint32_t soff = (uint32_t)(r * APITCH + half * 16);

    float acc[4][4][4];
    #pragma unroll
    for (int mi = 0; mi < 4; mi++)
        #pragma unroll
        for (int ni = 0; ni < 4; ni++)
            #pragma unroll
            for (int e = 0; e < 4; e++) acc[mi][ni][e] = 0.0f;

    {
        unsigned short* b0 = sm;
        *(uint4*)(b0 + soff)                 = *(const uint4*)(pAh);
        *(uint4*)(b0 + soff + 8)             = *(const uint4*)(pAh + 8);
        *(uint4*)(b0 + TILE_U16 + soff)      = *(const uint4*)(pAl);
        *(uint4*)(b0 + TILE_U16 + soff + 8)  = *(const uint4*)(pAl + 8);
        *(uint4*)(b0 + 2*TILE_U16 + soff)    = *(const uint4*)(pBh);
        *(uint4*)(b0 + 2*TILE_U16 + soff + 8)= *(const uint4*)(pBh + 8);
        *(uint4*)(b0 + 3*TILE_U16 + soff)    = *(const uint4*)(pBl);
        *(uint4*)(b0 + 3*TILE_U16 + soff + 8)= *(const uint4*)(pBl + 8);
    }
    __syncthreads();

    for (int t = 0; t < NT_STEPS; t++) {
        const int cur = t & 1;
        const bool has_next = (t + 1) < NT_STEPS;
        uint4 nAh0, nAh1, nAl0, nAl1, nBh0, nBh1, nBl0, nBl1;
        if (has_next) {
            const int kn = (t + 1) * KTILE;
            nAh0 = *(const uint4*)(pAh + kn); nAh1 = *(const uint4*)(pAh + kn + 8);
            nAl0 = *(const uint4*)(pAl + kn); nAl1 = *(const uint4*)(pAl + kn + 8);
            nBh0 = *(const uint4*)(pBh + kn); nBh1 = *(const uint4*)(pBh + kn + 8);
            nBl0 = *(const uint4*)(pBl + kn); nBl1 = *(const uint4*)(pBl + kn + 8);
        }

        // smem byte bases for the 4 arrays of this buffer
        const uint32_t aH = sbase + 2u * (uint32_t)(cur * BUF_U16);
        const uint32_t aL = aH + 2u * TILE_U16;
        const uint32_t bH = aH + 4u * TILE_U16;
        const uint32_t bL = aH + 6u * TILE_U16;

        #pragma unroll
        for (int ks = 0; ks < KTILE; ks += 16) {
            uint32_t ah[4][4], al[4][4], bh[2][4], bl[2][4];
            #pragma unroll
            for (int mi = 0; mi < 4; mi++) {
                const uint32_t off = 2u * (uint32_t)((rowA0 + mi * 16) * APITCH + ks + oaC);
                ldsm_x4(ah[mi], aH + off);
                ldsm_x4(al[mi], aL + off);
            }
            #pragma unroll
            for (int jj = 0; jj < 2; jj++) {
                const uint32_t off = 2u * (uint32_t)((rowB0 + jj * 16) * APITCH + ks + obC);
                ldsm_x4(bh[jj], bH + off);
                ldsm_x4(bl[jj], bL + off);
            }
            #pragma unroll
            for (int mi = 0; mi < 4; mi++)
                #pragma unroll
                for (int jj = 0; jj < 2; jj++) {
                    mma_bf16(acc[mi][2*jj],   ah[mi], &bh[jj][0]);
                    mma_bf16(acc[mi][2*jj],   ah[mi], &bl[jj][0]);
                    mma_bf16(acc[mi][2*jj],   al[mi], &bh[jj][0]);
                    mma_bf16(acc[mi][2*jj+1], ah[mi], &bh[jj][2]);
                    mma_bf16(acc[mi][2*jj+1], ah[mi], &bl[jj][2]);
                    mma_bf16(acc[mi][2*jj+1], al[mi], &bh[jj][2]);
                }
        }

        if (has_next) {
            unsigned short* bn = sm + (cur ^ 1) * BUF_U16;
            *(uint4*)(bn + soff)                  = nAh0;
            *(uint4*)(bn + soff + 8)              = nAh1;
            *(uint4*)(bn + TILE_U16 + soff)       = nAl0;
            *(uint4*)(bn + TILE_U16 + soff + 8)   = nAl1;
            *(uint4*)(bn + 2*TILE_U16 + soff)     = nBh0;
            *(uint4*)(bn + 2*TILE_U16 + soff + 8) = nBh1;
            *(uint4*)(bn + 3*TILE_U16 + soff)     = nBl0;
            *(uint4*)(bn + 3*TILE_U16 + soff + 8) = nBl1;
        }
        __syncthreads();
    }

    #pragma unroll
    for (int mi = 0; mi < 4; mi++) {
        const int mrow = row0 + wm * 64 + mi * 16 + g;
        #pragma unroll
        for (int ni = 0; ni < 4; ni++) {
            const int ncol = col0 + wn * 32 + ni * 8 + tq * 2;
            *(float2*)(C + (size_t)mrow * ldc + ncol)       = make_float2(acc[mi][ni][0], acc[mi][ni][1]);
            *(float2*)(C + (size_t)(mrow + 8) * ldc + ncol) = make_float2(acc[mi][ni][2], acc[mi][ni][3]);
        }
    }
}

__global__ void __launch_bounds__(256, 1)
qkv_tc(const unsigned short* xh, const unsigned short* xl,
       const unsigned short* wqh, const unsigned short* wql,
       const unsigned short* wkh, const unsigned short* wkl,
       const unsigned short* wvh, const unsigned short* wvl,
       float* q, float* k, float* v)
{
    const int bx = blockIdx.x;
    const unsigned short *Bh, *Bl; float* C; int ldc, col0;
    if (bx < 16)      { Bh = wqh; Bl = wql; C = q; ldc = 2048; col0 = bx * 128; }
    else if (bx < 20) { Bh = wkh; Bl = wkl; C = k; ldc = 512;  col0 = (bx - 16) * 128; }
    else              { Bh = wvh; Bl = wvl; C = v; ldc = 512;  col0 = (bx - 20) * 128; }
    gemm_mma_body(xh, xl, Bh, Bl, C, ldc, blockIdx.y * 128, col0);
}

__global__ void __launch_bounds__(256, 1)
out_tc(const unsigned short* oh, const unsigned short* ol,
       const unsigned short* woh, const unsigned short* wol, float* C)
{
    gemm_mma_body(oh, ol, woh, wol, C, 2048, blockIdx.y * 128, blockIdx.x * 128);
}

// ================= rope =================
__global__ void fill_rope_table()
{
    int idx = blockIdx.x * blockDim.x + threadIdx.x;
    if (idx >= S_LEN * 64) return;
    int d = idx & 63, pos = idx >> 6;
    double inv = pow(10000.0, -((double)(2 * d)) / 128.0);
    double cd, sd;
    sincos((double)pos * inv, &sd, &cd);
    g_rope_tab[idx] = make_float2((float)cd, (float)sd);
}

__global__ void rope_apply(float* __restrict__ t, int total, int nheads)
{
    int idx = blockIdx.x * blockDim.x + threadIdx.x;
    if (idx >= total) return;
    int d = idx & 63;
    int tmp = idx >> 6;
    int h = tmp % nheads;
    int row = tmp / nheads;
    int pos = row & (S_LEN - 1);
    float2 cs = g_rope_tab[pos * 64 + d];
    float* base = t + ((size_t)row * nheads + h) * HDIM;
    float x1 = base[d], x2 = base[d + 64];
    base[d]      = x1 * cs.x - x2 * cs.y;
    base[d + 64] = x2 * cs.x + x1 * cs.y;
}

// ================= flash attention via mma.sync, split-bf16 =================
#define AKP 136
#define AVP 72
#define SKH 0
#define SKL (64 * AKP)
#define SVH (2 * 64 * AKP)
#define SVL (2 * 64 * AKP + 128 * AVP)
#define ATT_SMEM ((2 * 64 * AKP + 2 * 128 * AVP) * 2)   // 71680 B

__global__ void __launch_bounds__(128)
attn_mma(const float* __restrict__ Q,
         const unsigned short* __restrict__ Kh, const unsigned short* __restrict__ Kl,
         const unsigned short* __restrict__ Vth, const unsigned short* __restrict__ Vtl,
         unsigned short* __restrict__ Oh, unsigned short* __restrict__ Ol)
{
    const int qt = blockIdx.x;
    const int h  = blockIdx.y;
    const int b  = blockIdx.z;
    const int g4 = h >> 2;
    const int bg = b * 4 + g4;

    extern __shared__ unsigned short smu[];
    const uint32_t sbase = smem_u32(smu);

    const int tid  = threadIdx.x;
    const int wid  = tid >> 5;
    const int lane = tid & 31;
    const int gr   = lane >> 2;
    const int tq   = lane & 3;

    const int lr    = lane & 7;
    const int off8a = (lane & 8)  ? 8 : 0;
    const int off8b = (lane & 16) ? 8 : 0;

    const int q0 = qt * 64 + wid * 16;
    const float* pq0 = Q + ((size_t)(b * S_LEN + q0 + gr) * 16 + h) * 128;
    const float* pq1 = Q + ((size_t)(b * S_LEN + q0 + gr + 8) * 16 + h) * 128;
    uint32_t qh[8][4], ql[8][4];
    #pragma unroll
    for (int ks = 0; ks < 8; ks++) {
        float2 x0 = *(const float2*)(pq0 + 16 * ks + 2 * tq);
        float2 x1 = *(const float2*)(pq1 + 16 * ks + 2 * tq);
        float2 x2 = *(const float2*)(pq0 + 16 * ks + 2 * tq + 8);
        float2 x3 = *(const float2*)(pq1 + 16 * ks + 2 * tq + 8);
        split_pack(x0.x * SCALE, x0.y * SCALE, qh[ks][0], ql[ks][0]);
        split_pack(x1.x * SCALE, x1.y * SCALE, qh[ks][1], ql[ks][1]);
        split_pack(x2.x * SCALE, x2.y * SCALE, qh[ks][2], ql[ks][2]);
        split_pack(x3.x * SCALE, x3.y * SCALE, qh[ks][3], ql[ks][3]);
    }

    float o[16][4];
    #pragma unroll
    for (int j = 0; j < 16; j++)
        #pragma unroll
        for (int e = 0; e < 4; e++) o[j][e] = 0.0f;
    float m0 = -1e30f, m1 = -1e30f, l0 = 0.0f, l1 = 0.0f;

    const unsigned short* kh_base = Kh + ((size_t)(b * S_LEN) * 4 + g4) * 128;
    const unsigned short* kl_base = Kl + ((size_t)(b * S_LEN) * 4 + g4) * 128;
    const unsigned short* vth_base = Vth + (size_t)bg * 128 * S_LEN;
    const unsigned short* vtl_base = Vtl + (size_t)bg * 128 * S_LEN;

    for (int kt = 0; kt <= qt; kt++) {
        __syncthreads();
        {
            const unsigned short* src_h = kh_base + (size_t)(kt * 64) * 512;
            const unsigned short* src_l = kl_base + (size_t)(kt * 64) * 512;
            #pragma unroll
            for (int i = 0; i < 8; i++) {
                int idx = tid + i * 128;
                int row = idx >> 4, seg = (idx & 15) * 8;
                *(uint4*)(smu + SKH + row * AKP + seg) = *(const uint4*)(src_h + (size_t)row * 512 + seg);
                *(uint4*)(smu + SKL + row * AKP + seg) = *(const uint4*)(src_l + (size_t)row * 512 + seg);
            }
            const unsigned short* sv_h = vth_base + kt * 64;
            const unsigned short* sv_l = vtl_base + kt * 64;
            #pragma unroll
            for (int i = 0; i < 8; i++) {
                int idx = tid + i * 128;
                int row = idx >> 3, seg = (idx & 7) * 8;
                *(uint4*)(smu + SVH + row * AVP + seg) = *(const uint4*)(sv_h + (size_t)row * S_LEN + seg);
                *(uint4*)(smu + SVL + row * AVP + seg) = *(const uint4*)(sv_l + (size_t)row * S_LEN + seg);
            }
        }
        __syncthreads();

        float s[8][4];
        #pragma unroll
        for (int j = 0; j < 8; j++)
            #pragma unroll
            for (int e = 0; e < 4; e++) s[j][e] = 0.0f;

        #pragma unroll
        for (int jj = 0; jj < 4; jj++) {
            #pragma unroll
            for (int ks = 0; ks < 8; ks++) {
                uint32_t bh[4], bl[4];
                uint32_t a_h = sbase + 2 * (uint32_t)(SKH + (16 * jj + off8b + lr) * AKP + 16 * ks + off8a);
                uint32_t a_l = sbase + 2 * (uint32_t)(SKL + (16 * jj + off8b + lr) * AKP + 16 * ks + off8a);
                ldsm_x4(bh, a_h);
                ldsm_x4(bl, a_l);
                mma_bf16(s[2*jj],   qh[ks], bh + 0);
                mma_bf16(s[2*jj],   qh[ks], bl + 0);
                mma_bf16(s[2*jj],   ql[ks], bh + 0);
                mma_bf16(s[2*jj+1], qh[ks], bh + 2);
                mma_bf16(s[2*jj+1], qh[ks], bl + 2);
                mma_bf16(s[2*jj+1], ql[ks], bh + 2);
            }
        }

        if (kt == qt) {
            const int rl0 = wid * 16 + gr;
            const int rl1 = rl0 + 8;
            #pragma unroll
            for (int j = 0; j < 8; j++) {
                int c0 = 8 * j + 2 * tq, c1 = c0 + 1;
                if (c0 > rl0) s[j][0] = -1e30f;
                if (c1 > rl0) s[j][1] = -1e30f;
                if (c0 > rl1) s[j][2] = -1e30f;
                if (c1 > rl1) s[j][3] = -1e30f;
            }
        }

        float mx0 = -1e30f, mx1 = -1e30f;
        #pragma unroll
        for (int j = 0; j < 8; j++) {
            mx0 = fmaxf(mx0, fmaxf(s[j][0], s[j][1]));
            mx1 = fmaxf(mx1, fmaxf(s[j][2], s[j][3]));
        }
        mx0 = fmaxf(mx0, __shfl_xor_sync(0xffffffffu, mx0, 1));
        mx0 = fmaxf(mx0, __shfl_xor_sync(0xffffffffu, mx0, 2));
        mx1 = fmaxf(mx1, __shfl_xor_sync(0xffffffffu, mx1, 1));
        mx1 = fmaxf(mx1, __shfl_xor_sync(0xffffffffu, mx1, 2));

        float mn0 = fmaxf(m0, mx0), mn1 = fmaxf(m1, mx1);
        float c0 = __expf(m0 - mn0), c1 = __expf(m1 - mn1);

        uint32_t ph[8][2], pl[8][2];
        float sum0 = 0.0f, sum1 = 0.0f;
        #pragma unroll
        for (int j = 0; j < 8; j++) {
            float p0 = __expf(s[j][0] - mn0);
            float p1 = __expf(s[j][1] - mn0);
            float p2 = __expf(s[j][2] - mn1);
            float p3 = __expf(s[j][3] - mn1);
            sum0 += p0 + p1;
            sum1 += p2 + p3;
            split_pack(p0, p1, ph[j][0], pl[j][0]);
            split_pack(p2, p3, ph[j][1], pl[j][1]);
        }
        sum0 += __shfl_xor_sync(0xffffffffu, sum0, 1);
        sum0 += __shfl_xor_sync(0xffffffffu, sum0, 2);
        sum1 += __shfl_xor_sync(0xffffffffu, sum1, 1);
        sum1 += __shfl_xor_sync(0xffffffffu, sum1, 2);
        l0 = l0 * c0 + sum0;
        l1 = l1 * c1 + sum1;
        m0 = mn0; m1 = mn1;
        #pragma unroll
        for (int j = 0; j < 16; j++) {
            o[j][0] *= c0; o[j][1] *= c0;
            o[j][2] *= c1; o[j][3] *= c1;
        }

        #pragma unroll
        for (int ks = 0; ks < 4; ks++) {
            uint32_t ah4[4] = { ph[2*ks][0], ph[2*ks][1], ph[2*ks+1][0], ph[2*ks+1][1] };
            uint32_t al4[4] = { pl[2*ks][0], pl[2*ks][1], pl[2*ks+1][0], pl[2*ks+1][1] };
            #pragma unroll
            for (int jj = 0; jj < 8; jj++) {
                uint32_t bh[4], bl[4];
                uint32_t a_h = sbase + 2 * (uint32_t)(SVH + (16 * jj + off8b + lr) * AVP + 16 * ks + off8a);
                uint32_t a_l = sbase + 2 * (uint32_t)(SVL + (16 * jj + off8b + lr) * AVP + 16 * ks + off8a);
                ldsm_x4(bh, a_h);
                ldsm_x4(bl, a_l);
                mma_bf16(o[2*jj],   ah4, bh + 0);
                mma_bf16(o[2*jj],   ah4, bl + 0);
                mma_bf16(o[2*jj],   al4, bh + 0);
                mma_bf16(o[2*jj+1], ah4, bh + 2);
                mma_bf16(o[2*jj+1], ah4, bl + 2);
                mma_bf16(o[2*jj+1], al4, bh + 2);
            }
        }
    }

    const float inv0 = 1.0f / l0, inv1 = 1.0f / l1;
    const size_t rowA = (size_t)(b * S_LEN + q0 + gr) * 2048 + h * 128;
    const size_t rowB = (size_t)(b * S_LEN + q0 + gr + 8) * 2048 + h * 128;
    #pragma unroll
    for (int j = 0; j < 16; j++) {
        const int col = 8 * j + 2 * tq;
        uint32_t h0, l0r, h1, l1r;
        split_pack(o[j][0] * inv0, o[j][1] * inv0, h0, l0r);
        split_pack(o[j][2] * inv1, o[j][3] * inv1, h1, l1r);
        *(uint32_t*)(Oh + rowA + col) = h0;
        *(uint32_t*)(Ol + rowA + col) = l0r;
        *(uint32_t*)(Oh + rowB + col) = h1;
        *(uint32_t*)(Ol + rowB + col) = l1r;
    }
}

// ================= launch =================
extern "C" void kernel_launch(void* const* d_in, const int* in_sizes, int n_in,
                              void* d_out, int out_size)
{
    const float* x  = (const float*)d_in[0];
    const float* wq = (const float*)d_in[1];
    const float* wk = (const float*)d_in[2];
    const float* wv = (const float*)d_in[3];
    const float* wo = (const float*)d_in[4];
    float* out = (float*)d_out;

    float *q_p, *k_p, *v_p;
    cudaGetSymbolAddress((void**)&q_p, g_q);
    cudaGetSymbolAddress((void**)&k_p, g_k);
    cudaGetSymbolAddress((void**)&v_p, g_v);
    unsigned short *xh, *xl, *oh, *ol, *wqh, *wql, *wkh, *wkl, *wvh, *wvl, *woh, *wol;
    unsigned short *kh, *kl, *vth, *vtl;
    cudaGetSymbolAddress((void**)&xh, g_xh);   cudaGetSymbolAddress((void**)&xl, g_xl);
    cudaGetSymbolAddress((void**)&oh, g_oh);   cudaGetSymbolAddress((void**)&ol, g_ol);
    cudaGetSymbolAddress((void**)&wqh, g_wqh); cudaGetSymbolAddress((void**)&wql, g_wql);
    cudaGetSymbolAddress((void**)&wkh, g_wkh); cudaGetSymbolAddress((void**)&wkl, g_wkl);
    cudaGetSymbolAddress((void**)&wvh, g_wvh); cudaGetSymbolAddress((void**)&wvl, g_wvl);
    cudaGetSymbolAddress((void**)&woh, g_woh); cudaGetSymbolAddress((void**)&wol, g_wol);
    cudaGetSymbolAddress((void**)&kh, g_kh);   cudaGetSymbolAddress((void**)&kl, g_kl);
    cudaGetSymbolAddress((void**)&vth, g_vth); cudaGetSymbolAddress((void**)&vtl, g_vtl);

    cudaFuncSetAttribute(qkv_tc, cudaFuncAttributeMaxDynamicSharedMemorySize, GEMM_SMEM);
    cudaFuncSetAttribute(out_tc, cudaFuncAttributeMaxDynamicSharedMemorySize, GEMM_SMEM);
    cudaFuncSetAttribute(attn_mma, cudaFuncAttributeMaxDynamicSharedMemorySize, ATT_SMEM);

    // 0. rope table + operand conversion
    fill_rope_table<<<(S_LEN * 64 + 255) / 256, 256>>>();
    {
        int tx = ROWS * HID;
        convert_split_k<<<(tx + 255) / 256, 256>>>(x, xh, xl, tx);
        transpose_split_k<<<dim3(2048 / 32, HID / 32), dim3(32, 8)>>>(wq, wqh, wql, HID, 2048);
        transpose_split_k<<<dim3(512 / 32,  HID / 32), dim3(32, 8)>>>(wk, wkh, wkl, HID, 512);
        transpose_split_k<<<dim3(512 / 32,  HID / 32), dim3(32, 8)>>>(wv, wvh, wvl, HID, 512);
        transpose_split_k<<<dim3(2048 / 32, HID / 32), dim3(32, 8)>>>(wo, woh, wol, HID, 2048);
    }

    // 1. fused QKV projections
    qkv_tc<<<dim3(24, ROWS / 128), 256, GEMM_SMEM>>>(xh, xl, wqh, wql, wkh, wkl, wvh, wvl,
                                                     q_p, k_p, v_p);

    // 2. RoPE on q, k; then split K; transpose+split V
    {
        int tq = ROWS * NHEAD * 64;
        rope_apply<<<(tq + 255) / 256, 256>>>(q_p, tq, NHEAD);
        int tk = ROWS * NKVH * 64;
        rope_apply<<<(tk + 255) / 256, 256>>>(k_p, tk, NKVH);
        int tke = ROWS * NKVH * HDIM;
        convert_split_k<<<(tke + 255) / 256, 256>>>(k_p, kh, kl, tke);
        vt_split<<<dim3(S_LEN / 32, HDIM / 32, BATCH * NKVH), dim3(32, 8)>>>(v_p, vth, vtl);
    }

    // 3. flash attention (mma.sync split-bf16); writes oh/ol directly
    attn_mma<<<dim3(S_LEN / 64, NHEAD, BATCH), 128, ATT_SMEM>>>(q_p, kh, kl, vth, vtl, oh, ol);

    // 4. output projection
    out_tc<<<dim3(HID / 128, ROWS / 128), 256, GEMM_SMEM>>>(oh, ol, woh, wol, out);
}

// round 8
// speedup vs baseline: 3.7509x; 1.0520x over previous
#include <cuda_runtime.h>
#include <cuda_bf16.h>
#include <cstdint>
#include <cstddef>

// ---------------- problem constants ----------------
#define S_LEN  2048
#define HID    2048
#define NHEAD  16
#define NKVH   4
#define HDIM   128
#define BATCH  2
#define ROWS   (BATCH * S_LEN)      // 4096
#define SCALE  0.08838834764831845f // 1/sqrt(128)

// ---------------- scratch (static device memory; no allocations) ----------------
__device__ float g_q[(size_t)ROWS * NHEAD * HDIM];
__device__ float g_k[(size_t)ROWS * NKVH  * HDIM];
__device__ float g_v[(size_t)ROWS * NKVH  * HDIM];
__device__ float2 g_rope_tab[(size_t)S_LEN * 64];

// split-bf16 operands
__device__ unsigned short g_xh[(size_t)ROWS * HID];
__device__ unsigned short g_xl[(size_t)ROWS * HID];
__device__ unsigned short g_oh[(size_t)ROWS * HID];
__device__ unsigned short g_ol[(size_t)ROWS * HID];
__device__ unsigned short g_wqh[(size_t)2048 * HID];
__device__ unsigned short g_wql[(size_t)2048 * HID];
__device__ unsigned short g_wkh[(size_t)512 * HID];
__device__ unsigned short g_wkl[(size_t)512 * HID];
__device__ unsigned short g_wvh[(size_t)512 * HID];
__device__ unsigned short g_wvl[(size_t)512 * HID];
__device__ unsigned short g_woh[(size_t)2048 * HID];
__device__ unsigned short g_wol[(size_t)2048 * HID];
// attention operands: K split (post-rope), V^T split
__device__ unsigned short g_kh[(size_t)ROWS * NKVH * HDIM];
__device__ unsigned short g_kl[(size_t)ROWS * NKVH * HDIM];
__device__ unsigned short g_vth[(size_t)BATCH * NKVH * HDIM * S_LEN];
__device__ unsigned short g_vtl[(size_t)BATCH * NKVH * HDIM * S_LEN];

// ================= mma.sync / ldmatrix / cp.async helpers =================
__device__ __forceinline__ void mma_bf16(float* c, const uint32_t* a, const uint32_t* b)
{
    asm volatile(
        "mma.sync.aligned.m16n8k16.row.col.f32.bf16.bf16.f32 "
        "{%0,%1,%2,%3}, {%4,%5,%6,%7}, {%8,%9}, {%0,%1,%2,%3};"
        : "+f"(c[0]), "+f"(c[1]), "+f"(c[2]), "+f"(c[3])
        : "r"(a[0]), "r"(a[1]), "r"(a[2]), "r"(a[3]), "r"(b[0]), "r"(b[1]));
}
__device__ __forceinline__ void ldsm_x4(uint32_t* r, uint32_t addr)
{
    asm volatile("ldmatrix.sync.aligned.m8n8.x4.shared.b16 {%0,%1,%2,%3}, [%4];"
        : "=r"(r[0]), "=r"(r[1]), "=r"(r[2]), "=r"(r[3]) : "r"(addr));
}
__device__ __forceinline__ uint32_t smem_u32(const void* p) {
    uint32_t a;
    asm("{ .reg .u64 t; cvta.to.shared.u64 t, %1; cvt.u32.u64 %0, t; }" : "=r"(a) : "l"(p));
    return a;
}
__device__ __forceinline__ void cp_async16(uint32_t dst, const void* src) {
    asm volatile("cp.async.cg.shared.global [%0], [%1], 16;" :: "r"(dst), "l"(src));
}
#define CP_COMMIT() asm volatile("cp.async.commit_group;" ::: "memory")
#define CP_WAIT1()  asm volatile("cp.async.wait_group 1;" ::: "memory")
#define CP_WAIT0()  asm volatile("cp.async.wait_group 0;" ::: "memory")

__device__ __forceinline__ unsigned short f2bf(float v) {
    __nv_bfloat16 b = __float2bfloat16(v);
    return *(unsigned short*)&b;
}
__device__ __forceinline__ float bf2f(unsigned short u) {
    __nv_bfloat16 b = *(__nv_bfloat16*)&u;
    return __bfloat162float(b);
}
__device__ __forceinline__ void split_pack(float a, float b, uint32_t& h, uint32_t& l)
{
    unsigned short ah = f2bf(a), bh = f2bf(b);
    unsigned short al = f2bf(a - bf2f(ah)), bl = f2bf(b - bf2f(bh));
    h = (uint32_t)ah | ((uint32_t)bh << 16);
    l = (uint32_t)al | ((uint32_t)bl << 16);
}

// ================= conversion kernels =================
__device__ __forceinline__ void bf16_split(float v, unsigned short& h, unsigned short& l) {
    __nv_bfloat16 hb = __float2bfloat16(v);
    __nv_bfloat16 lb = __float2bfloat16(v - __bfloat162float(hb));
    h = *(unsigned short*)&hb;
    l = *(unsigned short*)&lb;
}

__global__ void convert_split_k(const float* __restrict__ src,
                                unsigned short* __restrict__ hi,
                                unsigned short* __restrict__ lo, int total)
{
    int i = blockIdx.x * blockDim.x + threadIdx.x;
    if (i >= total) return;
    bf16_split(src[i], hi[i], lo[i]);
}

__global__ void transpose_split_k(const float* __restrict__ src,
                                  unsigned short* __restrict__ hi,
                                  unsigned short* __restrict__ lo, int K, int N)
{
    __shared__ float t[32][33];
    const int n0 = blockIdx.x * 32, k0 = blockIdx.y * 32;
    const int tx = threadIdx.x, ty = threadIdx.y;
    #pragma unroll
    for (int i = 0; i < 4; i++)
        t[ty + i * 8][tx] = src[(size_t)(k0 + ty + i * 8) * N + n0 + tx];
    __syncthreads();
    #pragma unroll
    for (int i = 0; i < 4; i++) {
        int n = ty + i * 8;
        float v = t[tx][n];
        unsigned short h, l;
        bf16_split(v, h, l);
        size_t o = (size_t)(n0 + n) * K + k0 + tx;
        hi[o] = h; lo[o] = l;
    }
}

__global__ void vt_split(const float* __restrict__ v,
                         unsigned short* __restrict__ vth,
                         unsigned short* __restrict__ vtl)
{
    __shared__ float t[32][33];
    const int bg = blockIdx.z;
    const int b = bg >> 2, g = bg & 3;
    const int key0 = blockIdx.x * 32, d0 = blockIdx.y * 32;
    const int tx = threadIdx.x, ty = threadIdx.y;
    #pragma unroll
    for (int i = 0; i < 4; i++)
        t[ty + i * 8][tx] = v[((size_t)(b * S_LEN + key0 + ty + i * 8) * 4 + g) * 128 + d0 + tx];
    __syncthreads();
    #pragma unroll
    for (int i = 0; i < 4; i++) {
        int dl = ty + i * 8;
        float val = t[tx][dl];
        unsigned short h, l;
        bf16_split(val, h, l);
        size_t o = ((size_t)bg * 128 + d0 + dl) * S_LEN + key0 + tx;
        vth[o] = h; vtl[o] = l;
    }
}

// ================= split-bf16 GEMM: mma.sync + ldmatrix + cp.async =================
#define KTILE    32
#define NT_STEPS (HID / KTILE)
#define APITCH   40
#define TILE_U16 (128 * APITCH)
#define BUF_U16  (4 * TILE_U16)
#define GEMM_SMEM (2 * BUF_U16 * 2)   // 81920 B

__device__ void gemm_mma_body(const unsigned short* __restrict__ Ah, const unsigned short* __restrict__ Al,
                              const unsigned short* __restrict__ Bh, const unsigned short* __restrict__ Bl,
                              float* __restrict__ C, int ldc, int row0, int col0)
{
    extern __shared__ unsigned short sm[];
    const uint32_t sbase = smem_u32(sm);
    const int tid  = threadIdx.x;
    const int wid  = tid >> 5;
    const int lane = tid & 31;
    const int wm   = wid & 1;
    const int wn   = wid >> 1;
    const int g    = lane >> 2;
    const int tq   = lane & 3;

    const int lr   = lane & 7;
    const int oaR  = (lane & 8)  ? 8 : 0;
    const int oaC  = (lane & 16) ? 8 : 0;
    const int obR  = (lane & 16) ? 8 : 0;
    const int obC  = (lane & 8)  ? 8 : 0;
    const int rowA0 = wm * 64 + lr + oaR;
    const int rowB0 = wn * 32 + lr + obR;

    const int r    = tid >> 1;
    const int half = tid & 1;
    const unsigned short* pAh = Ah + (size_t)(row0 + r) * HID + half * 16;
    const unsigned short* pAl = Al + (size_t)(row0 + r) * HID + half * 16;
    const unsigned short* pBh = Bh + (size_t)(col0 + r) * HID + half * 16;
    const unsigned short* pBl = Bl + (size_t)(col0 + r) * HID + half * 16;
    const uint32_t dsoff = 2u * (uint32_t)(r * APITCH + half * 16);   // bytes within array

    float acc[4][4][4];
    #pragma unroll
    for (int mi = 0; mi < 4; mi++)
        #pragma unroll
        for (int ni = 0; ni < 4; ni++)
            #pragma unroll
            for (int e = 0; e < 4; e++) acc[mi][ni][e] = 0.0f;

    // issue loads for k-tile t into buffer buf
    auto issue = [&](int t, int buf) {
        const int k0 = t * KTILE;
        const uint32_t b0 = sbase + 2u * (uint32_t)(buf * BUF_U16) + dsoff;
        cp_async16(b0,                       pAh + k0);
        cp_async16(b0 + 16,                  pAh + k0 + 8);
        cp_async16(b0 + 2u*TILE_U16,         pAl + k0);
        cp_async16(b0 + 2u*TILE_U16 + 16,    pAl + k0 + 8);
        cp_async16(b0 + 4u*TILE_U16,         pBh + k0);
        cp_async16(b0 + 4u*TILE_U16 + 16,    pBh + k0 + 8);
        cp_async16(b0 + 6u*TILE_U16,         pBl + k0);
        cp_async16(b0 + 6u*TILE_U16 + 16,    pBl + k0 + 8);
    };

    issue(0, 0);
    CP_COMMIT();

    for (int t = 0; t < NT_STEPS; t++) {
        const int cur = t & 1;
        const bool has_next = (t + 1) < NT_STEPS;
        if (has_next) {
            issue(t + 1, cur ^ 1);
            CP_COMMIT();
            CP_WAIT1();
        } else {
            CP_WAIT0();
        }
        __syncthreads();

        const uint32_t aH = sbase + 2u * (uint32_t)(cur * BUF_U16);
        const uint32_t aL = aH + 2u * TILE_U16;
        const uint32_t bH = aH + 4u * TILE_U16;
        const uint32_t bL = aH + 6u * TILE_U16;

        #pragma unroll
        for (int ks = 0; ks < KTILE; ks += 16) {
            uint32_t bhf[2][4], blf[2][4];
            #pragma unroll
            for (int jj = 0; jj < 2; jj++) {
                const uint32_t off = 2u * (uint32_t)((rowB0 + jj * 16) * APITCH + ks + obC);
                ldsm_x4(bhf[jj], bH + off);
                ldsm_x4(blf[jj], bL + off);
            }
            #pragma unroll
            for (int mi = 0; mi < 4; mi++) {
                uint32_t ahf[4], alf[4];
                const uint32_t off = 2u * (uint32_t)((rowA0 + mi * 16) * APITCH + ks + oaC);
                ldsm_x4(ahf, aH + off);
                ldsm_x4(alf, aL + off);
                #pragma unroll
                for (int jj = 0; jj < 2; jj++) {
                    mma_bf16(acc[mi][2*jj],   ahf, &bhf[jj][0]);
                    mma_bf16(acc[mi][2*jj],   ahf, &blf[jj][0]);
                    mma_bf16(acc[mi][2*jj],   alf, &bhf[jj][0]);
                    mma_bf16(acc[mi][2*jj+1], ahf, &bhf[jj][2]);
                    mma_bf16(acc[mi][2*jj+1], ahf, &blf[jj][2]);
                    mma_bf16(acc[mi][2*jj+1], alf, &bhf[jj][2]);
                }
            }
        }
        __syncthreads();   // buffer cur is free to be overwritten next iteration
    }

    #pragma unroll
    for (int mi = 0; mi < 4; mi++) {
        const int mrow = row0 + wm * 64 + mi * 16 + g;
        #pragma unroll
        for (int ni = 0; ni < 4; ni++) {
            const int ncol = col0 + wn * 32 + ni * 8 + tq * 2;
            *(float2*)(C + (size_t)mrow * ldc + ncol)       = make_float2(acc[mi][ni][0], acc[mi][ni][1]);
            *(float2*)(C + (size_t)(mrow + 8) * ldc + ncol) = make_float2(acc[mi][ni][2], acc[mi][ni][3]);
        }
    }
}

__global__ void __launch_bounds__(256, 2)
qkv_tc(const unsigned short* xh, const unsigned short* xl,
       const unsigned short* wqh, const unsigned short* wql,
       const unsigned short* wkh, const unsigned short* wkl,
       const unsigned short* wvh, const unsigned short* wvl,
       float* q, float* k, float* v)
{
    const int bx = blockIdx.x;
    const unsigned short *Bh, *Bl; float* C; int ldc, col0;
    if (bx < 16)      { Bh = wqh; Bl = wql; C = q; ldc = 2048; col0 = bx * 128; }
    else if (bx < 20) { Bh = wkh; Bl = wkl; C = k; ldc = 512;  col0 = (bx - 16) * 128; }
    else              { Bh = wvh; Bl = wvl; C = v; ldc = 512;  col0 = (bx - 20) * 128; }
    gemm_mma_body(xh, xl, Bh, Bl, C, ldc, blockIdx.y * 128, col0);
}

__global__ void __launch_bounds__(256, 2)
out_tc(const unsigned short* oh, const unsigned short* ol,
       const unsigned short* woh, const unsigned short* wol, float* C)
{
    gemm_mma_body(oh, ol, woh, wol, C, 2048, blockIdx.y * 128, blockIdx.x * 128);
}

// ================= rope =================
__global__ void fill_rope_table()
{
    int idx = blockIdx.x * blockDim.x + threadIdx.x;
    if (idx >= S_LEN * 64) return;
    int d = idx & 63, pos = idx >> 6;
    double inv = pow(10000.0, -((double)(2 * d)) / 128.0);
    double cd, sd;
    sincos((double)pos * inv, &sd, &cd);
    g_rope_tab[idx] = make_float2((float)cd, (float)sd);
}

__global__ void rope_apply(float* __restrict__ t, int total, int nheads)
{
    int idx = blockIdx.x * blockDim.x + threadIdx.x;
    if (idx >= total) return;
    int d = idx & 63;
    int tmp = idx >> 6;
    int h = tmp % nheads;
    int row = tmp / nheads;
    int pos = row & (S_LEN - 1);
    float2 cs = g_rope_tab[pos * 64 + d];
    float* base = t + ((size_t)row * nheads + h) * HDIM;
    float x1 = base[d], x2 = base[d + 64];
    base[d]      = x1 * cs.x - x2 * cs.y;
    base[d + 64] = x2 * cs.x + x1 * cs.y;
}

// ================= flash attention via mma.sync, split-bf16 =================
#define AKP 136
#define AVP 72
#define SKH 0
#define SKL (64 * AKP)
#define SVH (2 * 64 * AKP)
#define SVL (2 * 64 * AKP + 128 * AVP)
#define ATT_SMEM ((2 * 64 * AKP + 2 * 128 * AVP) * 2)   // 71680 B

__global__ void __launch_bounds__(128)
attn_mma(const float* __restrict__ Q,
         const unsigned short* __restrict__ Kh, const unsigned short* __restrict__ Kl,
         const unsigned short* __restrict__ Vth, const unsigned short* __restrict__ Vtl,
         unsigned short* __restrict__ Oh, unsigned short* __restrict__ Ol)
{
    const int qt = blockIdx.x;
    const int h  = blockIdx.y;
    const int b  = blockIdx.z;
    const int g4 = h >> 2;
    const int bg = b * 4 + g4;

    extern __shared__ unsigned short smu[];
    const uint32_t sbase = smem_u32(smu);

    const int tid  = threadIdx.x;
    const int wid  = tid >> 5;
    const int lane = tid & 31;
    const int gr   = lane >> 2;
    const int tq   = lane & 3;

    const int lr    = lane & 7;
    const int off8a = (lane & 8)  ? 8 : 0;
    const int off8b = (lane & 16) ? 8 : 0;

    const int q0 = qt * 64 + wid * 16;
    const float* pq0 = Q + ((size_t)(b * S_LEN + q0 + gr) * 16 + h) * 128;
    const float* pq1 = Q + ((size_t)(b * S_LEN + q0 + gr + 8) * 16 + h) * 128;
    uint32_t qh[8][4], ql[8][4];
    #pragma unroll
    for (int ks = 0; ks < 8; ks++) {
        float2 x0 = *(const float2*)(pq0 + 16 * ks + 2 * tq);
        float2 x1 = *(const float2*)(pq1 + 16 * ks + 2 * tq);
        float2 x2 = *(const float2*)(pq0 + 16 * ks + 2 * tq + 8);
        float2 x3 = *(const float2*)(pq1 + 16 * ks + 2 * tq + 8);
        split_pack(x0.x * SCALE, x0.y * SCALE, qh[ks][0], ql[ks][0]);
        split_pack(x1.x * SCALE, x1.y * SCALE, qh[ks][1], ql[ks][1]);
        split_pack(x2.x * SCALE, x2.y * SCALE, qh[ks][2], ql[ks][2]);
        split_pack(x3.x * SCALE, x3.y * SCALE, qh[ks][3], ql[ks][3]);
    }

    float o[16][4];
    #pragma unroll
    for (int j = 0; j < 16; j++)
        #pragma unroll
        for (int e = 0; e < 4; e++) o[j][e] = 0.0f;
    float m0 = -1e30f, m1 = -1e30f, l0 = 0.0f, l1 = 0.0f;

    const unsigned short* kh_base = Kh + ((size_t)(b * S_LEN) * 4 + g4) * 128;
    const unsigned short* kl_base = Kl + ((size_t)(b * S_LEN) * 4 + g4) * 128;
    const unsigned short* vth_base = Vth + (size_t)bg * 128 * S_LEN;
    const unsigned short* vtl_base = Vtl + (size_t)bg * 128 * S_LEN;

    for (int kt = 0; kt <= qt; kt++) {
        __syncthreads();
        {
            const unsigned short* src_h = kh_base + (size_t)(kt * 64) * 512;
            const unsigned short* src_l = kl_base + (size_t)(kt * 64) * 512;
            #pragma unroll
            for (int i = 0; i < 8; i++) {
                int idx = tid + i * 128;
                int row = idx >> 4, seg = (idx & 15) * 8;
                *(uint4*)(smu + SKH + row * AKP + seg) = *(const uint4*)(src_h + (size_t)row * 512 + seg);
                *(uint4*)(smu + SKL + row * AKP + seg) = *(const uint4*)(src_l + (size_t)row * 512 + seg);
            }
            const unsigned short* sv_h = vth_base + kt * 64;
            const unsigned short* sv_l = vtl_base + kt * 64;
            #pragma unroll
            for (int i = 0; i < 8; i++) {
                int idx = tid + i * 128;
                int row = idx >> 3, seg = (idx & 7) * 8;
                *(uint4*)(smu + SVH + row * AVP + seg) = *(const uint4*)(sv_h + (size_t)row * S_LEN + seg);
                *(uint4*)(smu + SVL + row * AVP + seg) = *(const uint4*)(sv_l + (size_t)row * S_LEN + seg);
            }
        }
        __syncthreads();

        float s[8][4];
        #pragma unroll
        for (int j = 0; j < 8; j++)
            #pragma unroll
            for (int e = 0; e < 4; e++) s[j][e] = 0.0f;

        #pragma unroll
        for (int jj = 0; jj < 4; jj++) {
            #pragma unroll
            for (int ks = 0; ks < 8; ks++) {
                uint32_t bh[4], bl[4];
                uint32_t a_h = sbase + 2 * (uint32_t)(SKH + (16 * jj + off8b + lr) * AKP + 16 * ks + off8a);
                uint32_t a_l = sbase + 2 * (uint32_t)(SKL + (16 * jj + off8b + lr) * AKP + 16 * ks + off8a);
                ldsm_x4(bh, a_h);
                ldsm_x4(bl, a_l);
                mma_bf16(s[2*jj],   qh[ks], bh + 0);
                mma_bf16(s[2*jj],   qh[ks], bl + 0);
                mma_bf16(s[2*jj],   ql[ks], bh + 0);
                mma_bf16(s[2*jj+1], qh[ks], bh + 2);
                mma_bf16(s[2*jj+1], qh[ks], bl + 2);
                mma_bf16(s[2*jj+1], ql[ks], bh + 2);
            }
        }

        if (kt == qt) {
            const int rl0 = wid * 16 + gr;
            const int rl1 = rl0 + 8;
            #pragma unroll
            for (int j = 0; j < 8; j++) {
                int c0 = 8 * j + 2 * tq, c1 = c0 + 1;
                if (c0 > rl0) s[j][0] = -1e30f;
                if (c1 > rl0) s[j][1] = -1e30f;
                if (c0 > rl1) s[j][2] = -1e30f;
                if (c1 > rl1) s[j][3] = -1e30f;
            }
        }

        float mx0 = -1e30f, mx1 = -1e30f;
        #pragma unroll
        for (int j = 0; j < 8; j++) {
            mx0 = fmaxf(mx0, fmaxf(s[j][0], s[j][1]));
            mx1 = fmaxf(mx1, fmaxf(s[j][2], s[j][3]));
        }
        mx0 = fmaxf(mx0, __shfl_xor_sync(0xffffffffu, mx0, 1));
        mx0 = fmaxf(mx0, __shfl_xor_sync(0xffffffffu, mx0, 2));
        mx1 = fmaxf(mx1, __shfl_xor_sync(0xffffffffu, mx1, 1));
        mx1 = fmaxf(mx1, __shfl_xor_sync(0xffffffffu, mx1, 2));

        float mn0 = fmaxf(m0, mx0), mn1 = fmaxf(m1, mx1);
        float c0 = __expf(m0 - mn0), c1 = __expf(m1 - mn1);

        uint32_t ph[8][2], pl[8][2];
        float sum0 = 0.0f, sum1 = 0.0f;
        #pragma unroll
        for (int j = 0; j < 8; j++) {
            float p0 = __expf(s[j][0] - mn0);
            float p1 = __expf(s[j][1] - mn0);
            float p2 = __expf(s[j][2] - mn1);
            float p3 = __expf(s[j][3] - mn1);
            sum0 += p0 + p1;
            sum1 += p2 + p3;
            split_pack(p0, p1, ph[j][0], pl[j][0]);
            split_pack(p2, p3, ph[j][1], pl[j][1]);
        }
        sum0 += __shfl_xor_sync(0xffffffffu, sum0, 1);
        sum0 += __shfl_xor_sync(0xffffffffu, sum0, 2);
        sum1 += __shfl_xor_sync(0xffffffffu, sum1, 1);
        sum1 += __shfl_xor_sync(0xffffffffu, sum1, 2);
        l0 = l0 * c0 + sum0;
        l1 = l1 * c1 + sum1;
        m0 = mn0; m1 = mn1;
        #pragma unroll
        for (int j = 0; j < 16; j++) {
            o[j][0] *= c0; o[j][1] *= c0;
            o[j][2] *= c1; o[j][3] *= c1;
        }

        #pragma unroll
        for (int ks = 0; ks < 4; ks++) {
            uint32_t ah4[4] = { ph[2*ks][0], ph[2*ks][1], ph[2*ks+1][0], ph[2*ks+1][1] };
            uint32_t al4[4] = { pl[2*ks][0], pl[2*ks][1], pl[2*ks+1][0], pl[2*ks+1][1] };
            #pragma unroll
            for (int jj = 0; jj < 8; jj++) {
                uint32_t bh[4], bl[4];
                uint32_t a_h = sbase + 2 * (uint32_t)(SVH + (16 * jj + off8b + lr) * AVP + 16 * ks + off8a);
                uint32_t a_l = sbase + 2 * (uint32_t)(SVL + (16 * jj + off8b + lr) * AVP + 16 * ks + off8a);
                ldsm_x4(bh, a_h);
                ldsm_x4(bl, a_l);
                mma_bf16(o[2*jj],   ah4, bh + 0);
                mma_bf16(o[2*jj],   ah4, bl + 0);
                mma_bf16(o[2*jj],   al4, bh + 0);
                mma_bf16(o[2*jj+1], ah4, bh + 2);
                mma_bf16(o[2*jj+1], ah4, bl + 2);
                mma_bf16(o[2*jj+1], al4, bh + 2);
            }
        }
    }

    const float inv0 = 1.0f / l0, inv1 = 1.0f / l1;
    const size_t rowA = (size_t)(b * S_LEN + q0 + gr) * 2048 + h * 128;
    const size_t rowB = (size_t)(b * S_LEN + q0 + gr + 8) * 2048 + h * 128;
    #pragma unroll
    for (int j = 0; j < 16; j++) {
        const int col = 8 * j + 2 * tq;
        uint32_t h0, l0r, h1, l1r;
        split_pack(o[j][0] * inv0, o[j][1] * inv0, h0, l0r);
        split_pack(o[j][2] * inv1, o[j][3] * inv1, h1, l1r);
        *(uint32_t*)(Oh + rowA + col) = h0;
        *(uint32_t*)(Ol + rowA + col) = l0r;
        *(uint32_t*)(Oh + rowB + col) = h1;
        *(uint32_t*)(Ol + rowB + col) = l1r;
    }
}

// ================= launch =================
extern "C" void kernel_launch(void* const* d_in, const int* in_sizes, int n_in,
                              void* d_out, int out_size)
{
    const float* x  = (const float*)d_in[0];
    const float* wq = (const float*)d_in[1];
    const float* wk = (const float*)d_in[2];
    const float* wv = (const float*)d_in[3];
    const float* wo = (const float*)d_in[4];
    float* out = (float*)d_out;

    float *q_p, *k_p, *v_p;
    cudaGetSymbolAddress((void**)&q_p, g_q);
    cudaGetSymbolAddress((void**)&k_p, g_k);
    cudaGetSymbolAddress((void**)&v_p, g_v);
    unsigned short *xh, *xl, *oh, *ol, *wqh, *wql, *wkh, *wkl, *wvh, *wvl, *woh, *wol;
    unsigned short *kh, *kl, *vth, *vtl;
    cudaGetSymbolAddress((void**)&xh, g_xh);   cudaGetSymbolAddress((void**)&xl, g_xl);
    cudaGetSymbolAddress((void**)&oh, g_oh);   cudaGetSymbolAddress((void**)&ol, g_ol);
    cudaGetSymbolAddress((void**)&wqh, g_wqh); cudaGetSymbolAddress((void**)&wql, g_wql);
    cudaGetSymbolAddress((void**)&wkh, g_wkh); cudaGetSymbolAddress((void**)&wkl, g_wkl);
    cudaGetSymbolAddress((void**)&wvh, g_wvh); cudaGetSymbolAddress((void**)&wvl, g_wvl);
    cudaGetSymbolAddress((void**)&woh, g_woh); cudaGetSymbolAddress((void**)&wol, g_wol);
    cudaGetSymbolAddress((void**)&kh, g_kh);   cudaGetSymbolAddress((void**)&kl, g_kl);
    cudaGetSymbolAddress((void**)&vth, g_vth); cudaGetSymbolAddress((void**)&vtl, g_vtl);

    cudaFuncSetAttribute(qkv_tc, cudaFuncAttributeMaxDynamicSharedMemorySize, GEMM_SMEM);
    cudaFuncSetAttribute(out_tc, cudaFuncAttributeMaxDynamicSharedMemorySize, GEMM_SMEM);
    cudaFuncSetAttribute(attn_mma, cudaFuncAttributeMaxDynamicSharedMemorySize, ATT_SMEM);

    // 0. rope table + operand conversion
    fill_rope_table<<<(S_LEN * 64 + 255) / 256, 256>>>();
    {
        int tx = ROWS * HID;
        convert_split_k<<<(tx + 255) / 256, 256>>>(x, xh, xl, tx);
        transpose_split_k<<<dim3(2048 / 32, HID / 32), dim3(32, 8)>>>(wq, wqh, wql, HID, 2048);
        transpose_split_k<<<dim3(512 / 32,  HID / 32), dim3(32, 8)>>>(wk, wkh, wkl, HID, 512);
        transpose_split_k<<<dim3(512 / 32,  HID / 32), dim3(32, 8)>>>(wv, wvh, wvl, HID, 512);
        transpose_split_k<<<dim3(2048 / 32, HID / 32), dim3(32, 8)>>>(wo, woh, wol, HID, 2048);
    }

    // 1. fused QKV projections
    qkv_tc<<<dim3(24, ROWS / 128), 256, GEMM_SMEM>>>(xh, xl, wqh, wql, wkh, wkl, wvh, wvl,
                                                     q_p, k_p, v_p);

    // 2. RoPE on q, k; then split K; transpose+split V
    {
        int tq = ROWS * NHEAD * 64;
        rope_apply<<<(tq + 255) / 256, 256>>>(q_p, tq, NHEAD);
        int tk = ROWS * NKVH * 64;
        rope_apply<<<(tk + 255) / 256, 256>>>(k_p, tk, NKVH);
        int tke = ROWS * NKVH * HDIM;
        convert_split_k<<<(tke + 255) / 256, 256>>>(k_p, kh, kl, tke);
        vt_split<<<dim3(S_LEN / 32, HDIM / 32, BATCH * NKVH), dim3(32, 8)>>>(v_p, vth, vtl);
    }

    // 3. flash attention (mma.sync split-bf16); writes oh/ol directly
    attn_mma<<<dim3(S_LEN / 64, NHEAD, BATCH), 128, ATT_SMEM>>>(q_p, kh, kl, vth, vtl, oh, ol);

    // 4. output projection
    out_tc<<<dim3(HID / 128, ROWS / 128), 256, GEMM_SMEM>>>(oh, ol, woh, wol, out);
}

// round 9
// speedup vs baseline: 7.5263x; 2.0065x over previous
#include <cuda_runtime.h>
#include <cuda_fp16.h>
#include <cstdint>
#include <cstddef>

// ---------------- problem constants ----------------
#define S_LEN  2048
#define HID    2048
#define NHEAD  16
#define NKVH   4
#define HDIM   128
#define BATCH  2
#define ROWS   (BATCH * S_LEN)      // 4096
#define SCALE  0.08838834764831845f // 1/sqrt(128)

// ---------------- scratch (static device memory; no allocations) ----------------
__device__ float g_q[(size_t)ROWS * NHEAD * HDIM];
__device__ float g_k[(size_t)ROWS * NKVH  * HDIM];
__device__ float g_v[(size_t)ROWS * NKVH  * HDIM];
__device__ float2 g_rope_tab[(size_t)S_LEN * 64];

// fp16 operands (single precision-level, no splits)
__device__ unsigned short g_xh[(size_t)ROWS * HID];
__device__ unsigned short g_oh[(size_t)ROWS * HID];
__device__ unsigned short g_wqh[(size_t)2048 * HID];
__device__ unsigned short g_wkh[(size_t)512 * HID];
__device__ unsigned short g_wvh[(size_t)512 * HID];
__device__ unsigned short g_woh[(size_t)2048 * HID];
__device__ unsigned short g_kh[(size_t)ROWS * NKVH * HDIM];
__device__ unsigned short g_vth[(size_t)BATCH * NKVH * HDIM * S_LEN];

// ================= mma.sync / ldmatrix / cp.async helpers =================
__device__ __forceinline__ void mma_f16(float* c, const uint32_t* a, const uint32_t* b)
{
    asm volatile(
        "mma.sync.aligned.m16n8k16.row.col.f32.f16.f16.f32 "
        "{%0,%1,%2,%3}, {%4,%5,%6,%7}, {%8,%9}, {%0,%1,%2,%3};"
        : "+f"(c[0]), "+f"(c[1]), "+f"(c[2]), "+f"(c[3])
        : "r"(a[0]), "r"(a[1]), "r"(a[2]), "r"(a[3]), "r"(b[0]), "r"(b[1]));
}
__device__ __forceinline__ void ldsm_x4(uint32_t* r, uint32_t addr)
{
    asm volatile("ldmatrix.sync.aligned.m8n8.x4.shared.b16 {%0,%1,%2,%3}, [%4];"
        : "=r"(r[0]), "=r"(r[1]), "=r"(r[2]), "=r"(r[3]) : "r"(addr));
}
__device__ __forceinline__ uint32_t smem_u32(const void* p) {
    uint32_t a;
    asm("{ .reg .u64 t; cvta.to.shared.u64 t, %1; cvt.u32.u64 %0, t; }" : "=r"(a) : "l"(p));
    return a;
}
__device__ __forceinline__ void cp_async16(uint32_t dst, const void* src) {
    asm volatile("cp.async.cg.shared.global [%0], [%1], 16;" :: "r"(dst), "l"(src));
}
#define CP_COMMIT() asm volatile("cp.async.commit_group;" ::: "memory")
#define CP_WAIT1()  asm volatile("cp.async.wait_group 1;" ::: "memory")
#define CP_WAIT0()  asm volatile("cp.async.wait_group 0;" ::: "memory")

__device__ __forceinline__ unsigned short f2h(float v) {
    __half h = __float2half_rn(v);
    return *(unsigned short*)&h;
}
__device__ __forceinline__ uint32_t pack2h(float a, float b) {
    __half2 h = __floats2half2_rn(a, b);
    return *(uint32_t*)&h;
}

// ================= conversion kernels =================
__global__ void convert_h(const float* __restrict__ src,
                          unsigned short* __restrict__ dst, int total)
{
    int i = blockIdx.x * blockDim.x + threadIdx.x;
    if (i >= total) return;
    dst[i] = f2h(src[i]);
}

// src [K][N] fp32 -> dst [N][K] fp16 (transpose)
__global__ void transpose_h(const float* __restrict__ src,
                            unsigned short* __restrict__ dst, int K, int N)
{
    __shared__ float t[32][33];
    const int n0 = blockIdx.x * 32, k0 = blockIdx.y * 32;
    const int tx = threadIdx.x, ty = threadIdx.y;  // (32, 8)
    #pragma unroll
    for (int i = 0; i < 4; i++)
        t[ty + i * 8][tx] = src[(size_t)(k0 + ty + i * 8) * N + n0 + tx];
    __syncthreads();
    #pragma unroll
    for (int i = 0; i < 4; i++) {
        int n = ty + i * 8;
        dst[(size_t)(n0 + n) * K + k0 + tx] = f2h(t[tx][n]);
    }
}

// V [(b*S+key)*4+g][128] fp32 -> vth [bg][d][2048] fp16 (transpose)
__global__ void vt_h(const float* __restrict__ v, unsigned short* __restrict__ vth)
{
    __shared__ float t[32][33];
    const int bg = blockIdx.z;
    const int b = bg >> 2, g = bg & 3;
    const int key0 = blockIdx.x * 32, d0 = blockIdx.y * 32;
    const int tx = threadIdx.x, ty = threadIdx.y;  // (32, 8)
    #pragma unroll
    for (int i = 0; i < 4; i++)
        t[ty + i * 8][tx] = v[((size_t)(b * S_LEN + key0 + ty + i * 8) * 4 + g) * 128 + d0 + tx];
    __syncthreads();
    #pragma unroll
    for (int i = 0; i < 4; i++) {
        int dl = ty + i * 8;
        vth[((size_t)bg * 128 + d0 + dl) * S_LEN + key0 + tx] = f2h(t[tx][dl]);
    }
}

// ================= fp16 GEMM: mma.sync + ldmatrix + cp.async =================
// C[128x128] CTA tile; C = A[M][2048] x B^T (B stored [N][2048]).
#define KTILE    64
#define NT_STEPS (HID / KTILE)      // 32
#define APITCH   72                 // u16 per smem row: 144B, LDSM conflict-free
#define TILE_U16 (128 * APITCH)     // 9216
#define BUF_U16  (2 * TILE_U16)     // A + B
#define GEMM_SMEM (2 * BUF_U16 * 2) // 73728 B

__device__ void gemm_mma_body(const unsigned short* __restrict__ Ah,
                              const unsigned short* __restrict__ Bh,
                              float* __restrict__ C, int ldc, int row0, int col0)
{
    extern __shared__ unsigned short sm[];
    const uint32_t sbase = smem_u32(sm);
    const int tid  = threadIdx.x;
    const int wid  = tid >> 5;
    const int lane = tid & 31;
    const int wm   = wid & 1;
    const int wn   = wid >> 1;
    const int g    = lane >> 2;
    const int tq   = lane & 3;

    const int lr   = lane & 7;
    const int oaR  = (lane & 8)  ? 8 : 0;
    const int oaC  = (lane & 16) ? 8 : 0;
    const int obR  = (lane & 16) ? 8 : 0;
    const int obC  = (lane & 8)  ? 8 : 0;
    const int rowA0 = wm * 64 + lr + oaR;
    const int rowB0 = wn * 32 + lr + obR;

    // loader: thread covers row r, 64B segment `half` (64 u16 per row = KTILE)
    const int r    = tid >> 1;
    const int half = tid & 1;
    const unsigned short* pA = Ah + (size_t)(row0 + r) * HID + half * 32;
    const unsigned short* pB = Bh + (size_t)(col0 + r) * HID + half * 32;
    const uint32_t dsoff = 2u * (uint32_t)(r * APITCH + half * 32);   // bytes

    float acc[4][4][4];
    #pragma unroll
    for (int mi = 0; mi < 4; mi++)
        #pragma unroll
        for (int ni = 0; ni < 4; ni++)
            #pragma unroll
            for (int e = 0; e < 4; e++) acc[mi][ni][e] = 0.0f;

    auto issue = [&](int t, int buf) {
        const int k0 = t * KTILE;
        const uint32_t a0 = sbase + 2u * (uint32_t)(buf * BUF_U16) + dsoff;
        const uint32_t b0 = a0 + 2u * TILE_U16;
        cp_async16(a0,      pA + k0);
        cp_async16(a0 + 16, pA + k0 + 8);
        cp_async16(a0 + 32, pA + k0 + 16);
        cp_async16(a0 + 48, pA + k0 + 24);
        cp_async16(b0,      pB + k0);
        cp_async16(b0 + 16, pB + k0 + 8);
        cp_async16(b0 + 32, pB + k0 + 16);
        cp_async16(b0 + 48, pB + k0 + 24);
    };

    issue(0, 0);
    CP_COMMIT();

    for (int t = 0; t < NT_STEPS; t++) {
        const int cur = t & 1;
        const bool has_next = (t + 1) < NT_STEPS;
        if (has_next) {
            issue(t + 1, cur ^ 1);
            CP_COMMIT();
            CP_WAIT1();
        } else {
            CP_WAIT0();
        }
        __syncthreads();

        const uint32_t aH = sbase + 2u * (uint32_t)(cur * BUF_U16);
        const uint32_t bH = aH + 2u * TILE_U16;

        #pragma unroll
        for (int ks = 0; ks < KTILE; ks += 16) {
            uint32_t bhf[2][4];
            #pragma unroll
            for (int jj = 0; jj < 2; jj++)
                ldsm_x4(bhf[jj], bH + 2u * (uint32_t)((rowB0 + jj * 16) * APITCH + ks + obC));
            #pragma unroll
            for (int mi = 0; mi < 4; mi++) {
                uint32_t ahf[4];
                ldsm_x4(ahf, aH + 2u * (uint32_t)((rowA0 + mi * 16) * APITCH + ks + oaC));
                #pragma unroll
                for (int jj = 0; jj < 2; jj++) {
                    mma_f16(acc[mi][2*jj],   ahf, &bhf[jj][0]);
                    mma_f16(acc[mi][2*jj+1], ahf, &bhf[jj][2]);
                }
            }
        }
        __syncthreads();
    }

    #pragma unroll
    for (int mi = 0; mi < 4; mi++) {
        const int mrow = row0 + wm * 64 + mi * 16 + g;
        #pragma unroll
        for (int ni = 0; ni < 4; ni++) {
            const int ncol = col0 + wn * 32 + ni * 8 + tq * 2;
            *(float2*)(C + (size_t)mrow * ldc + ncol)       = make_float2(acc[mi][ni][0], acc[mi][ni][1]);
            *(float2*)(C + (size_t)(mrow + 8) * ldc + ncol) = make_float2(acc[mi][ni][2], acc[mi][ni][3]);
        }
    }
}

__global__ void __launch_bounds__(256, 2)
qkv_tc(const unsigned short* xh,
       const unsigned short* wqh, const unsigned short* wkh, const unsigned short* wvh,
       float* q, float* k, float* v)
{
    const int bx = blockIdx.x;
    const unsigned short* Bh; float* C; int ldc, col0;
    if (bx < 16)      { Bh = wqh; C = q; ldc = 2048; col0 = bx * 128; }
    else if (bx < 20) { Bh = wkh; C = k; ldc = 512;  col0 = (bx - 16) * 128; }
    else              { Bh = wvh; C = v; ldc = 512;  col0 = (bx - 20) * 128; }
    gemm_mma_body(xh, Bh, C, ldc, blockIdx.y * 128, col0);
}

__global__ void __launch_bounds__(256, 2)
out_tc(const unsigned short* oh, const unsigned short* woh, float* C)
{
    gemm_mma_body(oh, woh, C, 2048, blockIdx.y * 128, blockIdx.x * 128);
}

// ================= rope =================
__global__ void fill_rope_table()
{
    int idx = blockIdx.x * blockDim.x + threadIdx.x;
    if (idx >= S_LEN * 64) return;
    int d = idx & 63, pos = idx >> 6;
    double inv = pow(10000.0, -((double)(2 * d)) / 128.0);
    double cd, sd;
    sincos((double)pos * inv, &sd, &cd);
    g_rope_tab[idx] = make_float2((float)cd, (float)sd);
}

__global__ void rope_apply(float* __restrict__ t, int total, int nheads)
{
    int idx = blockIdx.x * blockDim.x + threadIdx.x;
    if (idx >= total) return;
    int d = idx & 63;
    int tmp = idx >> 6;
    int h = tmp % nheads;
    int row = tmp / nheads;
    int pos = row & (S_LEN - 1);
    float2 cs = g_rope_tab[pos * 64 + d];
    float* base = t + ((size_t)row * nheads + h) * HDIM;
    float x1 = base[d], x2 = base[d + 64];
    base[d]      = x1 * cs.x - x2 * cs.y;
    base[d + 64] = x2 * cs.x + x1 * cs.y;
}

// ================= flash attention via mma.sync fp16 =================
// grid (S/64, NH, B); block 128 (4 warps); warp owns 16 q rows; kv tile 64 keys.
#define AKP 136     // K smem pitch (u16): 272B
#define AVP 72      // V^T smem pitch (u16): 144B
#define SKH 0
#define SVH (64 * AKP)
#define ATT_SMEM ((64 * AKP + 128 * AVP) * 2)   // 35840 B

__global__ void __launch_bounds__(128)
attn_mma(const float* __restrict__ Q,
         const unsigned short* __restrict__ Kh,
         const unsigned short* __restrict__ Vth,
         unsigned short* __restrict__ Oh)
{
    const int qt = blockIdx.x;
    const int h  = blockIdx.y;
    const int b  = blockIdx.z;
    const int g4 = h >> 2;
    const int bg = b * 4 + g4;

    extern __shared__ unsigned short smu[];
    const uint32_t sbase = smem_u32(smu);

    const int tid  = threadIdx.x;
    const int wid  = tid >> 5;
    const int lane = tid & 31;
    const int gr   = lane >> 2;
    const int tq   = lane & 3;

    const int lr    = lane & 7;
    const int off8a = (lane & 8)  ? 8 : 0;
    const int off8b = (lane & 16) ? 8 : 0;

    // ---- Q fragments (fp16, pre-scaled) ----
    const int q0 = qt * 64 + wid * 16;
    const float* pq0 = Q + ((size_t)(b * S_LEN + q0 + gr) * 16 + h) * 128;
    const float* pq1 = Q + ((size_t)(b * S_LEN + q0 + gr + 8) * 16 + h) * 128;
    uint32_t qh[8][4];
    #pragma unroll
    for (int ks = 0; ks < 8; ks++) {
        float2 x0 = *(const float2*)(pq0 + 16 * ks + 2 * tq);
        float2 x1 = *(const float2*)(pq1 + 16 * ks + 2 * tq);
        float2 x2 = *(const float2*)(pq0 + 16 * ks + 2 * tq + 8);
        float2 x3 = *(const float2*)(pq1 + 16 * ks + 2 * tq + 8);
        qh[ks][0] = pack2h(x0.x * SCALE, x0.y * SCALE);
        qh[ks][1] = pack2h(x1.x * SCALE, x1.y * SCALE);
        qh[ks][2] = pack2h(x2.x * SCALE, x2.y * SCALE);
        qh[ks][3] = pack2h(x3.x * SCALE, x3.y * SCALE);
    }

    float o[16][4];
    #pragma unroll
    for (int j = 0; j < 16; j++)
        #pragma unroll
        for (int e = 0; e < 4; e++) o[j][e] = 0.0f;
    float m0 = -1e30f, m1 = -1e30f, l0 = 0.0f, l1 = 0.0f;

    const unsigned short* kh_base  = Kh  + ((size_t)(b * S_LEN) * 4 + g4) * 128;
    const unsigned short* vth_base = Vth + (size_t)bg * 128 * S_LEN;

    for (int kt = 0; kt <= qt; kt++) {
        __syncthreads();
        {
            const unsigned short* src_k = kh_base + (size_t)(kt * 64) * 512;
            #pragma unroll
            for (int i = 0; i < 8; i++) {
                int idx = tid + i * 128;
                int row = idx >> 4, seg = (idx & 15) * 8;
                *(uint4*)(smu + SKH + row * AKP + seg) = *(const uint4*)(src_k + (size_t)row * 512 + seg);
            }
            const unsigned short* src_v = vth_base + kt * 64;
            #pragma unroll
            for (int i = 0; i < 8; i++) {
                int idx = tid + i * 128;
                int row = idx >> 3, seg = (idx & 7) * 8;
                *(uint4*)(smu + SVH + row * AVP + seg) = *(const uint4*)(src_v + (size_t)row * S_LEN + seg);
            }
        }
        __syncthreads();

        // ---- scores ----
        float s[8][4];
        #pragma unroll
        for (int j = 0; j < 8; j++)
            #pragma unroll
            for (int e = 0; e < 4; e++) s[j][e] = 0.0f;

        #pragma unroll
        for (int jj = 0; jj < 4; jj++) {
            #pragma unroll
            for (int ks = 0; ks < 8; ks++) {
                uint32_t khf[4];
                ldsm_x4(khf, sbase + 2 * (uint32_t)(SKH + (16 * jj + off8b + lr) * AKP + 16 * ks + off8a));
                mma_f16(s[2*jj],   qh[ks], khf + 0);
                mma_f16(s[2*jj+1], qh[ks], khf + 2);
            }
        }

        if (kt == qt) {
            const int rl0 = wid * 16 + gr;
            const int rl1 = rl0 + 8;
            #pragma unroll
            for (int j = 0; j < 8; j++) {
                int c0 = 8 * j + 2 * tq, c1 = c0 + 1;
                if (c0 > rl0) s[j][0] = -1e30f;
                if (c1 > rl0) s[j][1] = -1e30f;
                if (c0 > rl1) s[j][2] = -1e30f;
                if (c1 > rl1) s[j][3] = -1e30f;
            }
        }

        // ---- online softmax ----
        float mx0 = -1e30f, mx1 = -1e30f;
        #pragma unroll
        for (int j = 0; j < 8; j++) {
            mx0 = fmaxf(mx0, fmaxf(s[j][0], s[j][1]));
            mx1 = fmaxf(mx1, fmaxf(s[j][2], s[j][3]));
        }
        mx0 = fmaxf(mx0, __shfl_xor_sync(0xffffffffu, mx0, 1));
        mx0 = fmaxf(mx0, __shfl_xor_sync(0xffffffffu, mx0, 2));
        mx1 = fmaxf(mx1, __shfl_xor_sync(0xffffffffu, mx1, 1));
        mx1 = fmaxf(mx1, __shfl_xor_sync(0xffffffffu, mx1, 2));

        float mn0 = fmaxf(m0, mx0), mn1 = fmaxf(m1, mx1);
        float c0 = __expf(m0 - mn0), c1 = __expf(m1 - mn1);

        uint32_t ph[8][2];
        float sum0 = 0.0f, sum1 = 0.0f;
        #pragma unroll
        for (int j = 0; j < 8; j++) {
            float p0 = __expf(s[j][0] - mn0);
            float p1 = __expf(s[j][1] - mn0);
            float p2 = __expf(s[j][2] - mn1);
            float p3 = __expf(s[j][3] - mn1);
            sum0 += p0 + p1;
            sum1 += p2 + p3;
            ph[j][0] = pack2h(p0, p1);
            ph[j][1] = pack2h(p2, p3);
        }
        sum0 += __shfl_xor_sync(0xffffffffu, sum0, 1);
        sum0 += __shfl_xor_sync(0xffffffffu, sum0, 2);
        sum1 += __shfl_xor_sync(0xffffffffu, sum1, 1);
        sum1 += __shfl_xor_sync(0xffffffffu, sum1, 2);
        l0 = l0 * c0 + sum0;
        l1 = l1 * c1 + sum1;
        m0 = mn0; m1 = mn1;
        #pragma unroll
        for (int j = 0; j < 16; j++) {
            o[j][0] *= c0; o[j][1] *= c0;
            o[j][2] *= c1; o[j][3] *= c1;
        }

        // ---- PV ----
        #pragma unroll
        for (int ks = 0; ks < 4; ks++) {
            uint32_t ah4[4] = { ph[2*ks][0], ph[2*ks][1], ph[2*ks+1][0], ph[2*ks+1][1] };
            #pragma unroll
            for (int jj = 0; jj < 8; jj++) {
                uint32_t vhf[4];
                ldsm_x4(vhf, sbase + 2 * (uint32_t)(SVH + (16 * jj + off8b + lr) * AVP + 16 * ks + off8a));
                mma_f16(o[2*jj],   ah4, vhf + 0);
                mma_f16(o[2*jj+1], ah4, vhf + 2);
            }
        }
    }

    // ---- epilogue: normalize, store fp16 ----
    const float inv0 = 1.0f / l0, inv1 = 1.0f / l1;
    const size_t rowA = (size_t)(b * S_LEN + q0 + gr) * 2048 + h * 128;
    const size_t rowB = (size_t)(b * S_LEN + q0 + gr + 8) * 2048 + h * 128;
    #pragma unroll
    for (int j = 0; j < 16; j++) {
        const int col = 8 * j + 2 * tq;
        *(uint32_t*)(Oh + rowA + col) = pack2h(o[j][0] * inv0, o[j][1] * inv0);
        *(uint32_t*)(Oh + rowB + col) = pack2h(o[j][2] * inv1, o[j][3] * inv1);
    }
}

// ================= launch =================
extern "C" void kernel_launch(void* const* d_in, const int* in_sizes, int n_in,
                              void* d_out, int out_size)
{
    const float* x  = (const float*)d_in[0];
    const float* wq = (const float*)d_in[1];
    const float* wk = (const float*)d_in[2];
    const float* wv = (const float*)d_in[3];
    const float* wo = (const float*)d_in[4];
    float* out = (float*)d_out;

    float *q_p, *k_p, *v_p;
    cudaGetSymbolAddress((void**)&q_p, g_q);
    cudaGetSymbolAddress((void**)&k_p, g_k);
    cudaGetSymbolAddress((void**)&v_p, g_v);
    unsigned short *xh, *oh, *wqh, *wkh, *wvh, *woh, *kh, *vth;
    cudaGetSymbolAddress((void**)&xh, g_xh);
    cudaGetSymbolAddress((void**)&oh, g_oh);
    cudaGetSymbolAddress((void**)&wqh, g_wqh);
    cudaGetSymbolAddress((void**)&wkh, g_wkh);
    cudaGetSymbolAddress((void**)&wvh, g_wvh);
    cudaGetSymbolAddress((void**)&woh, g_woh);
    cudaGetSymbolAddress((void**)&kh, g_kh);
    cudaGetSymbolAddress((void**)&vth, g_vth);

    cudaFuncSetAttribute(qkv_tc, cudaFuncAttributeMaxDynamicSharedMemorySize, GEMM_SMEM);
    cudaFuncSetAttribute(out_tc, cudaFuncAttributeMaxDynamicSharedMemorySize, GEMM_SMEM);
    cudaFuncSetAttribute(attn_mma, cudaFuncAttributeMaxDynamicSharedMemorySize, ATT_SMEM);

    // 0. rope table + operand conversion
    fill_rope_table<<<(S_LEN * 64 + 255) / 256, 256>>>();
    {
        int tx = ROWS * HID;
        convert_h<<<(tx + 255) / 256, 256>>>(x, xh, tx);
        transpose_h<<<dim3(2048 / 32, HID / 32), dim3(32, 8)>>>(wq, wqh, HID, 2048);
        transpose_h<<<dim3(512 / 32,  HID / 32), dim3(32, 8)>>>(wk, wkh, HID, 512);
        transpose_h<<<dim3(512 / 32,  HID / 32), dim3(32, 8)>>>(wv, wvh, HID, 512);
        transpose_h<<<dim3(2048 / 32, HID / 32), dim3(32, 8)>>>(wo, woh, HID, 2048);
    }

    // 1. fused QKV projections (fp16 mma)
    qkv_tc<<<dim3(24, ROWS / 128), 256, GEMM_SMEM>>>(xh, wqh, wkh, wvh, q_p, k_p, v_p);

    // 2. RoPE on q, k; convert K; transpose V
    {
        int tq = ROWS * NHEAD * 64;
        rope_apply<<<(tq + 255) / 256, 256>>>(q_p, tq, NHEAD);
        int tk = ROWS * NKVH * 64;
        rope_apply<<<(tk + 255) / 256, 256>>>(k_p, tk, NKVH);
        int tke = ROWS * NKVH * HDIM;
        convert_h<<<(tke + 255) / 256, 256>>>(k_p, kh, tke);
        vt_h<<<dim3(S_LEN / 32, HDIM / 32, BATCH * NKVH), dim3(32, 8)>>>(v_p, vth);
    }

    // 3. flash attention (fp16 mma); writes oh directly
    attn_mma<<<dim3(S_LEN / 64, NHEAD, BATCH), 128, ATT_SMEM>>>(q_p, kh, vth, oh);

    // 4. output projection
    out_tc<<<dim3(HID / 128, ROWS / 128), 256, GEMM_SMEM>>>(oh, woh, out);
}

// round 10
// speedup vs baseline: 7.7147x; 1.0250x over previous
#include <cuda_runtime.h>
#include <cuda_fp16.h>
#include <cstdint>
#include <cstddef>

// ---------------- problem constants ----------------
#define S_LEN  2048
#define HID    2048
#define NHEAD  16
#define NKVH   4
#define HDIM   128
#define BATCH  2
#define ROWS   (BATCH * S_LEN)      // 4096
#define SCALE  0.08838834764831845f // 1/sqrt(128)

// ---------------- scratch (static device memory; no allocations) ----------------
__device__ float2 g_rope_tab[(size_t)S_LEN * 64];

// fp16 operands
__device__ unsigned short g_xh[(size_t)ROWS * HID];
__device__ unsigned short g_oh[(size_t)ROWS * HID];
__device__ unsigned short g_wqh[(size_t)2048 * HID];   // pre-scaled by SCALE
__device__ unsigned short g_wkh[(size_t)512 * HID];
__device__ unsigned short g_wvh[(size_t)512 * HID];
__device__ unsigned short g_woh[(size_t)2048 * HID];
__device__ unsigned short g_qh[(size_t)ROWS * NHEAD * HDIM];   // roped, scaled
__device__ unsigned short g_kh[(size_t)ROWS * NKVH * HDIM];    // roped
__device__ unsigned short g_vth[(size_t)BATCH * NKVH * HDIM * S_LEN];

// ================= mma.sync / ldmatrix / cp.async helpers =================
__device__ __forceinline__ void mma_f16(float* c, const uint32_t* a, const uint32_t* b)
{
    asm volatile(
        "mma.sync.aligned.m16n8k16.row.col.f32.f16.f16.f32 "
        "{%0,%1,%2,%3}, {%4,%5,%6,%7}, {%8,%9}, {%0,%1,%2,%3};"
        : "+f"(c[0]), "+f"(c[1]), "+f"(c[2]), "+f"(c[3])
        : "r"(a[0]), "r"(a[1]), "r"(a[2]), "r"(a[3]), "r"(b[0]), "r"(b[1]));
}
__device__ __forceinline__ void ldsm_x4(uint32_t* r, uint32_t addr)
{
    asm volatile("ldmatrix.sync.aligned.m8n8.x4.shared.b16 {%0,%1,%2,%3}, [%4];"
        : "=r"(r[0]), "=r"(r[1]), "=r"(r[2]), "=r"(r[3]) : "r"(addr));
}
__device__ __forceinline__ uint32_t smem_u32(const void* p) {
    uint32_t a;
    asm("{ .reg .u64 t; cvta.to.shared.u64 t, %1; cvt.u32.u64 %0, t; }" : "=r"(a) : "l"(p));
    return a;
}
__device__ __forceinline__ void cp_async16(uint32_t dst, const void* src) {
    asm volatile("cp.async.cg.shared.global [%0], [%1], 16;" :: "r"(dst), "l"(src));
}
#define CP_COMMIT() asm volatile("cp.async.commit_group;" ::: "memory")
#define CP_WAIT1()  asm volatile("cp.async.wait_group 1;" ::: "memory")
#define CP_WAIT0()  asm volatile("cp.async.wait_group 0;" ::: "memory")

__device__ __forceinline__ unsigned short f2h(float v) {
    __half h = __float2half_rn(v);
    return *(unsigned short*)&h;
}
__device__ __forceinline__ uint32_t pack2h(float a, float b) {
    __half2 h = __floats2half2_rn(a, b);
    return *(uint32_t*)&h;
}

// ================= conversion kernels =================
__global__ void convert_h(const float* __restrict__ src,
                          unsigned short* __restrict__ dst, int total)
{
    int i = blockIdx.x * blockDim.x + threadIdx.x;
    if (i >= total) return;
    dst[i] = f2h(src[i]);
}

// all 4 weight transposes in one launch. z: 0=wq(scaled) 1=wk 2=wv 3=wo
__global__ void transpose_all(const float* __restrict__ wq, const float* __restrict__ wk,
                              const float* __restrict__ wv, const float* __restrict__ wo,
                              unsigned short* __restrict__ wqh, unsigned short* __restrict__ wkh,
                              unsigned short* __restrict__ wvh, unsigned short* __restrict__ woh)
{
    const int z = blockIdx.z;
    const float* src; unsigned short* dst; int N; float scale = 1.0f;
    if (z == 0)      { src = wq; dst = wqh; N = 2048; scale = SCALE; }
    else if (z == 1) { src = wk; dst = wkh; N = 512; }
    else if (z == 2) { src = wv; dst = wvh; N = 512; }
    else             { src = wo; dst = woh; N = 2048; }
    if (blockIdx.x * 32 >= N) return;

    __shared__ float t[32][33];
    const int n0 = blockIdx.x * 32, k0 = blockIdx.y * 32;
    const int tx = threadIdx.x, ty = threadIdx.y;  // (32, 8)
    #pragma unroll
    for (int i = 0; i < 4; i++)
        t[ty + i * 8][tx] = src[(size_t)(k0 + ty + i * 8) * N + n0 + tx];
    __syncthreads();
    #pragma unroll
    for (int i = 0; i < 4; i++) {
        int n = ty + i * 8;
        dst[(size_t)(n0 + n) * HID + k0 + tx] = f2h(t[tx][n] * scale);
    }
}

// ================= rope table =================
__global__ void fill_rope_table()
{
    int idx = blockIdx.x * blockDim.x + threadIdx.x;
    if (idx >= S_LEN * 64) return;
    int d = idx & 63, pos = idx >> 6;
    double inv = pow(10000.0, -((double)(2 * d)) / 128.0);
    double cd, sd;
    sincos((double)pos * inv, &sd, &cd);
    g_rope_tab[idx] = make_float2((float)cd, (float)sd);
}

// ================= fp16 GEMM: mma.sync + ldmatrix + cp.async, fused epilogues =================
// C tile 128x128. modes: 0 = write fp32 C; 1 = rope + fp16 row-major; 2 = fp16 transposed (vth)
#define KTILE    64
#define NT_STEPS (HID / KTILE)      // 32
#define APITCH   72                 // u16 smem pitch (144B)
#define TILE_U16 (128 * APITCH)     // 9216
#define BUF_U16  (2 * TILE_U16)
#define GEMM_SMEM (2 * BUF_U16 * 2) // 73728 B
#define PITCHF   132                // fp32 staging pitch (epilogue)

__device__ void gemm_mma_body(const unsigned short* __restrict__ Ah,
                              const unsigned short* __restrict__ Bh,
                              int row0, int col0,
                              int mode,
                              float* __restrict__ C, int ldc,            // mode 0
                              unsigned short* __restrict__ O16, int ldo, // mode 1
                              unsigned short* __restrict__ VT, int bg)   // mode 2
{
    extern __shared__ unsigned short sm[];
    const uint32_t sbase = smem_u32(sm);
    const int tid  = threadIdx.x;
    const int wid  = tid >> 5;
    const int lane = tid & 31;
    const int wm   = wid & 1;
    const int wn   = wid >> 1;
    const int g    = lane >> 2;
    const int tq   = lane & 3;

    const int lr   = lane & 7;
    const int oaR  = (lane & 8)  ? 8 : 0;
    const int oaC  = (lane & 16) ? 8 : 0;
    const int obR  = (lane & 16) ? 8 : 0;
    const int obC  = (lane & 8)  ? 8 : 0;
    const int rowA0 = wm * 64 + lr + oaR;
    const int rowB0 = wn * 32 + lr + obR;

    const int r    = tid >> 1;
    const int half = tid & 1;
    const unsigned short* pA = Ah + (size_t)(row0 + r) * HID + half * 32;
    const unsigned short* pB = Bh + (size_t)(col0 + r) * HID + half * 32;
    const uint32_t dsoff = 2u * (uint32_t)(r * APITCH + half * 32);

    float acc[4][4][4];
    #pragma unroll
    for (int mi = 0; mi < 4; mi++)
        #pragma unroll
        for (int ni = 0; ni < 4; ni++)
            #pragma unroll
            for (int e = 0; e < 4; e++) acc[mi][ni][e] = 0.0f;

    auto issue = [&](int t, int buf) {
        const int k0 = t * KTILE;
        const uint32_t a0 = sbase + 2u * (uint32_t)(buf * BUF_U16) + dsoff;
        const uint32_t b0 = a0 + 2u * TILE_U16;
        cp_async16(a0,      pA + k0);
        cp_async16(a0 + 16, pA + k0 + 8);
        cp_async16(a0 + 32, pA + k0 + 16);
        cp_async16(a0 + 48, pA + k0 + 24);
        cp_async16(b0,      pB + k0);
        cp_async16(b0 + 16, pB + k0 + 8);
        cp_async16(b0 + 32, pB + k0 + 16);
        cp_async16(b0 + 48, pB + k0 + 24);
    };

    issue(0, 0);
    CP_COMMIT();

    for (int t = 0; t < NT_STEPS; t++) {
        const int cur = t & 1;
        const bool has_next = (t + 1) < NT_STEPS;
        if (has_next) {
            issue(t + 1, cur ^ 1);
            CP_COMMIT();
            CP_WAIT1();
        } else {
            CP_WAIT0();
        }
        __syncthreads();

        const uint32_t aH = sbase + 2u * (uint32_t)(cur * BUF_U16);
        const uint32_t bH = aH + 2u * TILE_U16;

        #pragma unroll
        for (int ks = 0; ks < KTILE; ks += 16) {
            uint32_t bhf[2][4];
            #pragma unroll
            for (int jj = 0; jj < 2; jj++)
                ldsm_x4(bhf[jj], bH + 2u * (uint32_t)((rowB0 + jj * 16) * APITCH + ks + obC));
            #pragma unroll
            for (int mi = 0; mi < 4; mi++) {
                uint32_t ahf[4];
                ldsm_x4(ahf, aH + 2u * (uint32_t)((rowA0 + mi * 16) * APITCH + ks + oaC));
                #pragma unroll
                for (int jj = 0; jj < 2; jj++) {
                    mma_f16(acc[mi][2*jj],   ahf, &bhf[jj][0]);
                    mma_f16(acc[mi][2*jj+1], ahf, &bhf[jj][2]);
                }
            }
        }
        __syncthreads();
    }

    if (mode == 0) {
        #pragma unroll
        for (int mi = 0; mi < 4; mi++) {
            const int mrow = row0 + wm * 64 + mi * 16 + g;
            #pragma unroll
            for (int ni = 0; ni < 4; ni++) {
                const int ncol = col0 + wn * 32 + ni * 8 + tq * 2;
                *(float2*)(C + (size_t)mrow * ldc + ncol)       = make_float2(acc[mi][ni][0], acc[mi][ni][1]);
                *(float2*)(C + (size_t)(mrow + 8) * ldc + ncol) = make_float2(acc[mi][ni][2], acc[mi][ni][3]);
            }
        }
        return;
    }

    // ---- stage fp32 accumulators into smem (buffers free after last sync) ----
    float* stf = (float*)sm;
    #pragma unroll
    for (int mi = 0; mi < 4; mi++) {
        const int rl = wm * 64 + mi * 16 + g;
        #pragma unroll
        for (int ni = 0; ni < 4; ni++) {
            const int cl = wn * 32 + ni * 8 + tq * 2;
            stf[rl * PITCHF + cl]           = acc[mi][ni][0];
            stf[rl * PITCHF + cl + 1]       = acc[mi][ni][1];
            stf[(rl + 8) * PITCHF + cl]     = acc[mi][ni][2];
            stf[(rl + 8) * PITCHF + cl + 1] = acc[mi][ni][3];
        }
    }
    __syncthreads();

    if (mode == 1) {
        // rope (pairs d, d+64 within this head tile) -> fp16 row-major
        const int rr = tid >> 1;
        const int dbase = (tid & 1) * 32;
        const int pos = (row0 + rr) & (S_LEN - 1);
        unsigned short b1[32], b2[32];
        #pragma unroll
        for (int i = 0; i < 32; i++) {
            const int d = dbase + i;
            float x1 = stf[rr * PITCHF + d];
            float x2 = stf[rr * PITCHF + d + 64];
            float2 cs = g_rope_tab[pos * 64 + d];
            b1[i] = f2h(x1 * cs.x - x2 * cs.y);
            b2[i] = f2h(x2 * cs.x + x1 * cs.y);
        }
        unsigned short* o1 = O16 + (size_t)(row0 + rr) * ldo + col0 + dbase;
        #pragma unroll
        for (int j = 0; j < 4; j++) *(uint4*)(o1 + j * 8)      = ((uint4*)b1)[j];
        #pragma unroll
        for (int j = 0; j < 4; j++) *(uint4*)(o1 + 64 + j * 8) = ((uint4*)b2)[j];
    } else {
        // mode 2: V -> transposed fp16 vth[(bg*128 + d) * S_LEN + key]
        const int d   = tid >> 1;
        const int kh2 = tid & 1;
        unsigned short vb[64];
        #pragma unroll
        for (int i = 0; i < 64; i++)
            vb[i] = f2h(stf[(kh2 * 64 + i) * PITCHF + d]);
        unsigned short* o = VT + ((size_t)bg * 128 + d) * S_LEN + (row0 & (S_LEN - 1)) + kh2 * 64;
        #pragma unroll
        for (int j = 0; j < 8; j++) *(uint4*)(o + j * 8) = ((uint4*)vb)[j];
    }
}

// fused QKV: grid.x 0..15 -> q heads, 16..19 -> k heads, 20..23 -> v heads
__global__ void __launch_bounds__(256, 2)
qkv_tc(const unsigned short* xh,
       const unsigned short* wqh, const unsigned short* wkh, const unsigned short* wvh,
       unsigned short* qh, unsigned short* kh, unsigned short* vth)
{
    const int bx = blockIdx.x;
    const int row0 = blockIdx.y * 128;
    if (bx < 16) {
        gemm_mma_body(xh, wqh, row0, bx * 128, 1, nullptr, 0, qh, 2048, nullptr, 0);
    } else if (bx < 20) {
        gemm_mma_body(xh, wkh, row0, (bx - 16) * 128, 1, nullptr, 0, kh, 512, nullptr, 0);
    } else {
        const int col0 = (bx - 20) * 128;
        const int bg = (row0 >> 11) * 4 + (col0 >> 7);
        gemm_mma_body(xh, wvh, row0, col0, 2, nullptr, 0, nullptr, 0, vth, bg);
    }
}

__global__ void __launch_bounds__(256, 2)
out_tc(const unsigned short* oh, const unsigned short* woh, float* C)
{
    gemm_mma_body(oh, woh, blockIdx.y * 128, blockIdx.x * 128, 0, C, 2048,
                  nullptr, 0, nullptr, 0);
}

// ================= flash attention via mma.sync fp16 =================
// grid (S/64, NH, B); block 128 (4 warps); warp owns 16 q rows; kv tile 64 keys.
#define AKP 136
#define AVP 72
#define SKH 0
#define SVH (64 * AKP)
#define ATT_SMEM ((64 * AKP + 128 * AVP) * 2)   // 35840 B

__global__ void __launch_bounds__(128)
attn_mma(const unsigned short* __restrict__ Qh,
         const unsigned short* __restrict__ Kh,
         const unsigned short* __restrict__ Vth,
         unsigned short* __restrict__ Oh)
{
    const int qt = blockIdx.x;
    const int h  = blockIdx.y;
    const int b  = blockIdx.z;
    const int g4 = h >> 2;
    const int bg = b * 4 + g4;

    extern __shared__ unsigned short smu[];
    const uint32_t sbase = smem_u32(smu);

    const int tid  = threadIdx.x;
    const int wid  = tid >> 5;
    const int lane = tid & 31;
    const int gr   = lane >> 2;
    const int tq   = lane & 3;

    const int lr    = lane & 7;
    const int off8a = (lane & 8)  ? 8 : 0;
    const int off8b = (lane & 16) ? 8 : 0;

    // ---- Q fragments: direct fp16 loads (pre-scaled, pre-roped) ----
    const int q0 = qt * 64 + wid * 16;
    const unsigned short* pq0 = Qh + (size_t)(b * S_LEN + q0 + gr) * 2048 + h * 128;
    const unsigned short* pq1 = Qh + (size_t)(b * S_LEN + q0 + gr + 8) * 2048 + h * 128;
    uint32_t qh[8][4];
    #pragma unroll
    for (int ks = 0; ks < 8; ks++) {
        qh[ks][0] = *(const uint32_t*)(pq0 + 16 * ks + 2 * tq);
        qh[ks][1] = *(const uint32_t*)(pq1 + 16 * ks + 2 * tq);
        qh[ks][2] = *(const uint32_t*)(pq0 + 16 * ks + 2 * tq + 8);
        qh[ks][3] = *(const uint32_t*)(pq1 + 16 * ks + 2 * tq + 8);
    }

    float o[16][4];
    #pragma unroll
    for (int j = 0; j < 16; j++)
        #pragma unroll
        for (int e = 0; e < 4; e++) o[j][e] = 0.0f;
    float m0 = -1e30f, m1 = -1e30f, l0 = 0.0f, l1 = 0.0f;

    const unsigned short* kh_base  = Kh  + ((size_t)(b * S_LEN) * 4 + g4) * 128;
    const unsigned short* vth_base = Vth + (size_t)bg * 128 * S_LEN;

    for (int kt = 0; kt <= qt; kt++) {
        __syncthreads();
        {
            const unsigned short* src_k = kh_base + (size_t)(kt * 64) * 512;
            #pragma unroll
            for (int i = 0; i < 8; i++) {
                int idx = tid + i * 128;
                int row = idx >> 4, seg = (idx & 15) * 8;
                *(uint4*)(smu + SKH + row * AKP + seg) = *(const uint4*)(src_k + (size_t)row * 512 + seg);
            }
            const unsigned short* src_v = vth_base + kt * 64;
            #pragma unroll
            for (int i = 0; i < 8; i++) {
                int idx = tid + i * 128;
                int row = idx >> 3, seg = (idx & 7) * 8;
                *(uint4*)(smu + SVH + row * AVP + seg) = *(const uint4*)(src_v + (size_t)row * S_LEN + seg);
            }
        }
        __syncthreads();

        // ---- scores ----
        float s[8][4];
        #pragma unroll
        for (int j = 0; j < 8; j++)
            #pragma unroll
            for (int e = 0; e < 4; e++) s[j][e] = 0.0f;

        #pragma unroll
        for (int jj = 0; jj < 4; jj++) {
            #pragma unroll
            for (int ks = 0; ks < 8; ks++) {
                uint32_t khf[4];
                ldsm_x4(khf, sbase + 2 * (uint32_t)(SKH + (16 * jj + off8b + lr) * AKP + 16 * ks + off8a));
                mma_f16(s[2*jj],   qh[ks], khf + 0);
                mma_f16(s[2*jj+1], qh[ks], khf + 2);
            }
        }

        if (kt == qt) {
            const int rl0 = wid * 16 + gr;
            const int rl1 = rl0 + 8;
            #pragma unroll
            for (int j = 0; j < 8; j++) {
                int c0 = 8 * j + 2 * tq, c1 = c0 + 1;
                if (c0 > rl0) s[j][0] = -1e30f;
                if (c1 > rl0) s[j][1] = -1e30f;
                if (c0 > rl1) s[j][2] = -1e30f;
                if (c1 > rl1) s[j][3] = -1e30f;
            }
        }

        // ---- online softmax ----
        float mx0 = -1e30f, mx1 = -1e30f;
        #pragma unroll
        for (int j = 0; j < 8; j++) {
            mx0 = fmaxf(mx0, fmaxf(s[j][0], s[j][1]));
            mx1 = fmaxf(mx1, fmaxf(s[j][2], s[j][3]));
        }
        mx0 = fmaxf(mx0, __shfl_xor_sync(0xffffffffu, mx0, 1));
        mx0 = fmaxf(mx0, __shfl_xor_sync(0xffffffffu, mx0, 2));
        mx1 = fmaxf(mx1, __shfl_xor_sync(0xffffffffu, mx1, 1));
        mx1 = fmaxf(mx1, __shfl_xor_sync(0xffffffffu, mx1, 2));

        float mn0 = fmaxf(m0, mx0), mn1 = fmaxf(m1, mx1);
        float c0 = __expf(m0 - mn0), c1 = __expf(m1 - mn1);

        uint32_t ph[8][2];
        float sum0 = 0.0f, sum1 = 0.0f;
        #pragma unroll
        for (int j = 0; j < 8; j++) {
            float p0 = __expf(s[j][0] - mn0);
            float p1 = __expf(s[j][1] - mn0);
            float p2 = __expf(s[j][2] - mn1);
            float p3 = __expf(s[j][3] - mn1);
            sum0 += p0 + p1;
            sum1 += p2 + p3;
            ph[j][0] = pack2h(p0, p1);
            ph[j][1] = pack2h(p2, p3);
        }
        sum0 += __shfl_xor_sync(0xffffffffu, sum0, 1);
        sum0 += __shfl_xor_sync(0xffffffffu, sum0, 2);
        sum1 += __shfl_xor_sync(0xffffffffu, sum1, 1);
        sum1 += __shfl_xor_sync(0xffffffffu, sum1, 2);
        l0 = l0 * c0 + sum0;
        l1 = l1 * c1 + sum1;
        m0 = mn0; m1 = mn1;
        #pragma unroll
        for (int j = 0; j < 16; j++) {
            o[j][0] *= c0; o[j][1] *= c0;
            o[j][2] *= c1; o[j][3] *= c1;
        }

        // ---- PV ----
        #pragma unroll
        for (int ks = 0; ks < 4; ks++) {
            uint32_t ah4[4] = { ph[2*ks][0], ph[2*ks][1], ph[2*ks+1][0], ph[2*ks+1][1] };
            #pragma unroll
            for (int jj = 0; jj < 8; jj++) {
                uint32_t vhf[4];
                ldsm_x4(vhf, sbase + 2 * (uint32_t)(SVH + (16 * jj + off8b + lr) * AVP + 16 * ks + off8a));
                mma_f16(o[2*jj],   ah4, vhf + 0);
                mma_f16(o[2*jj+1], ah4, vhf + 2);
            }
        }
    }

    // ---- epilogue: normalize, store fp16 ----
    const float inv0 = 1.0f / l0, inv1 = 1.0f / l1;
    const size_t rowA = (size_t)(b * S_LEN + q0 + gr) * 2048 + h * 128;
    const size_t rowB = (size_t)(b * S_LEN + q0 + gr + 8) * 2048 + h * 128;
    #pragma unroll
    for (int j = 0; j < 16; j++) {
        const int col = 8 * j + 2 * tq;
        *(uint32_t*)(Oh + rowA + col) = pack2h(o[j][0] * inv0, o[j][1] * inv0);
        *(uint32_t*)(Oh + rowB + col) = pack2h(o[j][2] * inv1, o[j][3] * inv1);
    }
}

// ================= launch =================
extern "C" void kernel_launch(void* const* d_in, const int* in_sizes, int n_in,
                              void* d_out, int out_size)
{
    const float* x  = (const float*)d_in[0];
    const float* wq = (const float*)d_in[1];
    const float* wk = (const float*)d_in[2];
    const float* wv = (const float*)d_in[3];
    const float* wo = (const float*)d_in[4];
    float* out = (float*)d_out;

    unsigned short *xh, *oh, *wqh, *wkh, *wvh, *woh, *qh, *kh, *vth;
    cudaGetSymbolAddress((void**)&xh, g_xh);
    cudaGetSymbolAddress((void**)&oh, g_oh);
    cudaGetSymbolAddress((void**)&wqh, g_wqh);
    cudaGetSymbolAddress((void**)&wkh, g_wkh);
    cudaGetSymbolAddress((void**)&wvh, g_wvh);
    cudaGetSymbolAddress((void**)&woh, g_woh);
    cudaGetSymbolAddress((void**)&qh, g_qh);
    cudaGetSymbolAddress((void**)&kh, g_kh);
    cudaGetSymbolAddress((void**)&vth, g_vth);

    cudaFuncSetAttribute(qkv_tc, cudaFuncAttributeMaxDynamicSharedMemorySize, GEMM_SMEM);
    cudaFuncSetAttribute(out_tc, cudaFuncAttributeMaxDynamicSharedMemorySize, GEMM_SMEM);
    cudaFuncSetAttribute(attn_mma, cudaFuncAttributeMaxDynamicSharedMemorySize, ATT_SMEM);

    // 0. rope table + operand conversion
    fill_rope_table<<<(S_LEN * 64 + 255) / 256, 256>>>();
    convert_h<<<(ROWS * HID + 255) / 256, 256>>>(x, xh, ROWS * HID);
    transpose_all<<<dim3(64, 64, 4), dim3(32, 8)>>>(wq, wk, wv, wo, wqh, wkh, wvh, woh);

    // 1. fused QKV projections + rope + quantize + V-transpose (epilogue-fused)
    qkv_tc<<<dim3(24, ROWS / 128), 256, GEMM_SMEM>>>(xh, wqh, wkh, wvh, qh, kh, vth);

    // 2. flash attention (fp16 mma); writes oh directly
    attn_mma<<<dim3(S_LEN / 64, NHEAD, BATCH), 128, ATT_SMEM>>>(qh, kh, vth, oh);

    // 3. output projection
    out_tc<<<dim3(HID / 128, ROWS / 128), 256, GEMM_SMEM>>>(oh, woh, out);
}